// round 5
// baseline (speedup 1.0000x reference)
#include <cuda_runtime.h>
#include <math.h>

#define BDIM 2
#define SEQ 2048
#define DMODEL 2048
#define NH 16
#define NKV 4
#define HD 128
#define NMOD 2
#define R_TOK (BDIM*SEQ)
#define KVE (NKV*HD)

/* GEMM tiling: CTA 128x256, 8 warps of 64x64, 3-stage cp.async */
#define BM 128
#define BN 256
#define BK 16
#define AP 20      /* A smem pitch */
#define BP2 264    /* B smem pitch */
#define NSTAGE 3
#define GEMM_SMEM_BYTES ((NSTAGE*BM*AP + NSTAGE*BK*BP2) * 4)

/* ---------------- scratch ---------------- */
__device__ int   g_cnt[NMOD];
__device__ int   g_tok[NMOD*R_TOK];
__device__ int   g_slot[R_TOK];
__device__ float g_wk[NMOD*DMODEL*KVE];
__device__ float g_wv[NMOD*DMODEL*KVE];
__device__ float g_xt[(size_t)NMOD*R_TOK*DMODEL];
__device__ float g_wqt[(size_t)NMOD*DMODEL*DMODEL];
__device__ float g_wot[(size_t)NMOD*DMODEL*DMODEL];
__device__ float g_q[(size_t)BDIM*NH*SEQ*HD];
__device__ float g_k[(size_t)BDIM*NKV*SEQ*HD];
__device__ float g_v[(size_t)BDIM*NKV*SEQ*HD];
__device__ float g_attn2[(size_t)NMOD*R_TOK*DMODEL];

/* ---------------- helpers ---------------- */
__device__ __forceinline__ float f2t(float f) {
    unsigned u;
    asm("cvt.rna.tf32.f32 %0, %1;" : "=r"(u) : "f"(f));
    return __uint_as_float(u);
}
__device__ __forceinline__ unsigned f2tu(float f) {
    unsigned u;
    asm("cvt.rna.tf32.f32 %0, %1;" : "=r"(u) : "f"(f));
    return u;
}
__device__ __forceinline__ void mma_tf32(float* d, const unsigned* a, const unsigned* b) {
    asm volatile(
        "mma.sync.aligned.m16n8k8.row.col.f32.tf32.tf32.f32 "
        "{%0,%1,%2,%3},{%4,%5,%6,%7},{%8,%9},{%0,%1,%2,%3};"
        : "+f"(d[0]), "+f"(d[1]), "+f"(d[2]), "+f"(d[3])
        : "r"(a[0]), "r"(a[1]), "r"(a[2]), "r"(a[3]), "r"(b[0]), "r"(b[1]));
}

#define CP16(dst, src) \
    asm volatile("cp.async.cg.shared.global [%0], [%1], 16;" :: "r"(dst), "l"(src))
#define CP_COMMIT() asm volatile("cp.async.commit_group;")
#define CP_WAIT(n)  asm volatile("cp.async.wait_group %0;" :: "n"(n))

/* ---------------- modality gather machinery ---------------- */
__global__ void zero_cnt_kernel() {
    if (threadIdx.x < NMOD) g_cnt[threadIdx.x] = 0;
}
__global__ void assign_kernel(const int* __restrict__ mid) {
    int t = blockIdx.x * blockDim.x + threadIdx.x;
    if (t < R_TOK) {
        int m = mid[t];
        int s = atomicAdd(&g_cnt[m], 1);
        g_tok[m * R_TOK + s] = t;
        g_slot[t] = m * R_TOK + s;
    }
}
__global__ void gather_x_kernel(const float* __restrict__ x) {
    int t = blockIdx.x;
    int dst = g_slot[t];
    const float4* src = (const float4*)(x + (size_t)t * DMODEL);
    float4* d = (float4*)(g_xt + (size_t)dst * DMODEL);
    for (int i = threadIdx.x; i < DMODEL / 4; i += blockDim.x) {
        float4 v = src[i];
        v.x = f2t(v.x); v.y = f2t(v.y); v.z = f2t(v.z); v.w = f2t(v.w);
        d[i] = v;
    }
}
__global__ void pad_kernel() {
    int m = blockIdx.y;
    int cnt = g_cnt[m];
    int ru = (cnt + BM - 1) & ~(BM - 1);
    int r = cnt + blockIdx.x;
    if (r >= ru) return;
    float4* a = (float4*)(g_xt + ((size_t)m * R_TOK + r) * DMODEL);
    float4* b = (float4*)(g_attn2 + ((size_t)m * R_TOK + r) * DMODEL);
    float4 z = make_float4(0.f, 0.f, 0.f, 0.f);
    for (int i = threadIdx.x; i < DMODEL / 4; i += blockDim.x) { a[i] = z; b[i] = z; }
}

/* ---------------- prepass ---------------- */
__global__ void prep_kernel(const float* __restrict__ Wq,
                            const float* __restrict__ Wo) {
    const int NE = NMOD * DMODEL * DMODEL;
    for (int i = blockIdx.x * blockDim.x + threadIdx.x; i < 2 * NE;
         i += gridDim.x * blockDim.x) {
        if (i < NE) g_wqt[i]      = f2t(Wq[i]);
        else        g_wot[i - NE] = f2t(Wo[i - NE]);
    }
}
__global__ void wsum_kernel(const float* __restrict__ Wk,
                            const float* __restrict__ Wv) {
    const int n = NMOD * DMODEL * KVE;
    const int half = DMODEL * KVE;
    for (int i = blockIdx.x * blockDim.x + threadIdx.x; i < n;
         i += gridDim.x * blockDim.x) {
        int m = i / half;
        int rest = i - m * half;
        size_t base = (size_t)m * 2 * half + rest;
        g_wk[i] = f2t(Wk[base] + Wk[base + half]);
        g_wv[i] = f2t(Wv[base] + Wv[base + half]);
    }
}

/* ---------------- 128x256 tf32 GEMM core, warp tile 64x64 ----------------- */
#define GEMM2_PROLOGUE()                                                      \
    const int tid = threadIdx.x;                                              \
    const int lane = tid & 31, w = tid >> 5;                                  \
    const int wm = (w >> 2) * 64, wn = (w & 3) * 64;                          \
    const int gid = lane >> 2, tig = lane & 3;                                \
    float* As = smem;                                                         \
    float* Bs = smem + NSTAGE * BM * AP;                                      \
    const unsigned sA = (unsigned)__cvta_generic_to_shared(As);               \
    const unsigned sB = (unsigned)__cvta_generic_to_shared(Bs);               \
    auto issue = [&](int buf, int k0) {                                       \
        unsigned aBase = sA + (unsigned)buf * (BM * AP * 4);                  \
        unsigned bBase = sB + (unsigned)buf * (BK * BP2 * 4);                 \
        _Pragma("unroll")                                                     \
        for (int q = 0; q < 2; q++) {                                         \
            int c = tid + q * 256;                                            \
            int r = c >> 2, kc = (c & 3) * 4;                                 \
            CP16(aBase + (r * AP + kc) * 4,                                   \
                 &X[(size_t)(row0 + r) * ldx + k0 + kc]);                     \
        }                                                                     \
        _Pragma("unroll")                                                     \
        for (int q = 0; q < 4; q++) {                                         \
            int c = tid * 4 + q;                                              \
            int kr = c >> 6, n4 = (c & 63) * 4;                               \
            CP16(bBase + (kr * BP2 + n4) * 4,                                 \
                 &W[(size_t)(k0 + kr) * ldw + col0 + n4]);                    \
        }                                                                     \
        CP_COMMIT();                                                          \
    };

__device__ __forceinline__ void gemm256(
    const float* __restrict__ X, int ldx,
    const float* __restrict__ W, int ldw,
    int Kdim, int row0, int col0,
    float (&acc)[4][8][4], float* smem)
{
    GEMM2_PROLOGUE();
    const int T = Kdim / BK;
    issue(0, 0);
    if (T > 1) issue(1, BK);
    for (int t = 0; t < T; t++) {
        const int buf = t % NSTAGE;
        if (t + 2 < T) { issue((t + 2) % NSTAGE, (t + 2) * BK); CP_WAIT(2); }
        else if (t + 1 < T) { CP_WAIT(1); }
        else { CP_WAIT(0); }
        __syncthreads();
        const float* Ab = As + buf * (BM * AP);
        const float* Bb = Bs + buf * (BK * BP2);
        #pragma unroll
        for (int kb = 0; kb < BK; kb += 8) {
            unsigned a[4][4], b[8][2];
            #pragma unroll
            for (int i = 0; i < 4; i++) {
                const float* ap = &Ab[(wm + i * 16 + gid) * AP + kb + tig];
                a[i][0] = __float_as_uint(ap[0]);
                a[i][1] = __float_as_uint(ap[8 * AP]);
                a[i][2] = __float_as_uint(ap[4]);
                a[i][3] = __float_as_uint(ap[8 * AP + 4]);
            }
            #pragma unroll
            for (int j = 0; j < 8; j++) {
                const float* bp = &Bb[(kb + tig) * BP2 + wn + j * 8 + gid];
                b[j][0] = __float_as_uint(bp[0]);
                b[j][1] = __float_as_uint(bp[4 * BP2]);
            }
            #pragma unroll
            for (int i = 0; i < 4; i++)
                #pragma unroll
                for (int j = 0; j < 8; j++)
                    mma_tf32(acc[i][j], a[i], b[j]);
        }
        __syncthreads();
    }
}

__device__ __forceinline__ void gemm256_splitA(
    const float* __restrict__ X, int ldx,
    const float* __restrict__ W, int ldw,
    int Kdim, int row0, int col0,
    float (&acc)[4][8][4], float* smem)
{
    GEMM2_PROLOGUE();
    const int T = Kdim / BK;
    issue(0, 0);
    if (T > 1) issue(1, BK);
    for (int t = 0; t < T; t++) {
        const int buf = t % NSTAGE;
        if (t + 2 < T) { issue((t + 2) % NSTAGE, (t + 2) * BK); CP_WAIT(2); }
        else if (t + 1 < T) { CP_WAIT(1); }
        else { CP_WAIT(0); }
        __syncthreads();
        const float* Ab = As + buf * (BM * AP);
        const float* Bb = Bs + buf * (BK * BP2);
        #pragma unroll
        for (int kb = 0; kb < BK; kb += 8) {
            unsigned b[8][2];
            #pragma unroll
            for (int j = 0; j < 8; j++) {
                const float* bp = &Bb[(kb + tig) * BP2 + wn + j * 8 + gid];
                b[j][0] = __float_as_uint(bp[0]);
                b[j][1] = __float_as_uint(bp[4 * BP2]);
            }
            #pragma unroll
            for (int i = 0; i < 4; i++) {
                const float* ap = &Ab[(wm + i * 16 + gid) * AP + kb + tig];
                float v[4] = {ap[0], ap[8 * AP], ap[4], ap[8 * AP + 4]};
                unsigned ah[4], al[4];
                #pragma unroll
                for (int q = 0; q < 4; q++) {
                    ah[q] = f2tu(v[q]);
                    al[q] = f2tu(v[q] - __uint_as_float(ah[q]));
                }
                #pragma unroll
                for (int j = 0; j < 8; j++) {
                    mma_tf32(acc[i][j], ah, b[j]);
                    mma_tf32(acc[i][j], al, b[j]);
                }
            }
        }
        __syncthreads();
    }
}

/* ---------------- Q projection + RoPE ---------------- */
__global__ void __launch_bounds__(256, 1) proj_q_kernel(
    const float* __restrict__ fc)
{
    extern __shared__ float smem[];
    const int m = blockIdx.z;
    const int cnt = g_cnt[m];
    const int row0 = blockIdx.y * BM, col0 = blockIdx.x * BN;
    if (row0 >= cnt) return;
    float acc[4][8][4] = {};
    gemm256(g_xt + (size_t)m * R_TOK * DMODEL, DMODEL,
            g_wqt + (size_t)m * DMODEL * DMODEL, DMODEL,
            DMODEL, row0, col0, acc, smem);

    const int lane = threadIdx.x & 31, w = threadIdx.x >> 5;
    const int wm = (w >> 2) * 64, wn = (w & 3) * 64;
    const int gid = lane >> 2, tig = lane & 3;
    #pragma unroll
    for (int i = 0; i < 4; i++) {
        #pragma unroll
        for (int half = 0; half < 2; half++) {
            int r = row0 + wm + i * 16 + gid + half * 8;
            if (r >= cnt) continue;
            int tok = g_tok[m * R_TOK + r];
            int b_ = tok >> 11, s = tok & (SEQ - 1);
            #pragma unroll
            for (int j = 0; j < 8; j++) {
                int c = col0 + wn + j * 8 + tig * 2;
                float e = acc[i][j][half * 2 + 0];
                float o = acc[i][j][half * 2 + 1];
                int h = c >> 7, d = c & 127, pr = d >> 1;
                float cv = fc[(size_t)s * 256 + pr * 4 + 0];
                float sv = fc[(size_t)s * 256 + pr * 4 + 2];
                size_t base = (((size_t)b_ * NH + h) * SEQ + s) * HD + d;
                g_q[base]     = e * cv + o * sv;
                g_q[base + 1] = o * cv - e * sv;
            }
        }
    }
}

/* ---------------- K/V projection (+RoPE on K) ---------------- */
__global__ void __launch_bounds__(256, 1) proj_kv_kernel(
    const float* __restrict__ fc)
{
    extern __shared__ float smem[];
    const int m = blockIdx.z;
    const int cnt = g_cnt[m];
    const int row0 = blockIdx.y * BM;
    if (row0 >= cnt) return;
    const int n0 = blockIdx.x * BN;           /* 0,256 -> K ; 512,768 -> V */
    const bool isV = (n0 >= KVE);
    const float* W = (isV ? g_wv : g_wk) + (size_t)m * DMODEL * KVE;
    const int c0base = isV ? n0 - KVE : n0;

    float acc[4][8][4] = {};
    gemm256(g_xt + (size_t)m * R_TOK * DMODEL, DMODEL,
            W, KVE, DMODEL, row0, c0base, acc, smem);

    const int lane = threadIdx.x & 31, w = threadIdx.x >> 5;
    const int wm = (w >> 2) * 64, wn = (w & 3) * 64;
    const int gid = lane >> 2, tig = lane & 3;
    #pragma unroll
    for (int i = 0; i < 4; i++) {
        #pragma unroll
        for (int half = 0; half < 2; half++) {
            int r = row0 + wm + i * 16 + gid + half * 8;
            if (r >= cnt) continue;
            int tok = g_tok[m * R_TOK + r];
            int b_ = tok >> 11, s = tok & (SEQ - 1);
            #pragma unroll
            for (int j = 0; j < 8; j++) {
                int c = c0base + wn + j * 8 + tig * 2;
                int kvh = c >> 7, d = c & 127;
                float e = acc[i][j][half * 2 + 0];
                float o = acc[i][j][half * 2 + 1];
                size_t base = (((size_t)b_ * NKV + kvh) * SEQ + s) * HD + d;
                if (!isV) {
                    int pr = d >> 1;
                    float cv = fc[(size_t)s * 256 + pr * 4 + 0];
                    float sv = fc[(size_t)s * 256 + pr * 4 + 2];
                    g_k[base]     = e * cv + o * sv;
                    g_k[base + 1] = o * cv - e * sv;
                } else {
                    g_v[base]     = e;
                    g_v[base + 1] = o;
                }
            }
        }
    }
}

/* ---------------- flash attention, tf32 tensor cores ---------------- */
#define KP 132
#define VP 136
#define PP 68
#define ATTN_SMEM ((64*KP + 64*VP + 64*PP) * 4)

__global__ void __launch_bounds__(128, 2) attn_kernel() {
    extern __shared__ float sm[];
    float* Ks = sm;
    float* Vs = Ks + 64 * KP;
    float* Ps = Vs + 64 * VP;

    const int qt = blockIdx.x, h = blockIdx.y, b = blockIdx.z;
    const int kvh = h >> 2;
    const int tid = threadIdx.x;
    const int w = tid >> 5, lane = tid & 31, gid = lane >> 2, tig = lane & 3;
    const float scale = 0.08838834764831845f;

    const float* Qg = g_q + (((size_t)b * NH + h) * SEQ + qt * 64 + w * 16) * HD;
    unsigned QA[16][4];
    #pragma unroll
    for (int ks = 0; ks < 16; ks++) {
        QA[ks][0] = f2tu(Qg[gid * HD + 8 * ks + tig] * scale);
        QA[ks][1] = f2tu(Qg[(gid + 8) * HD + 8 * ks + tig] * scale);
        QA[ks][2] = f2tu(Qg[gid * HD + 8 * ks + tig + 4] * scale);
        QA[ks][3] = f2tu(Qg[(gid + 8) * HD + 8 * ks + tig + 4] * scale);
    }

    float o[16][4];
    #pragma unroll
    for (int n = 0; n < 16; n++)
        #pragma unroll
        for (int q = 0; q < 4; q++) o[n][q] = 0.f;
    float mo[2] = {-1e30f, -1e30f}, l[2] = {0.f, 0.f};

    const float* Kg = g_k + ((size_t)b * NKV + kvh) * SEQ * HD;
    const float* Vg = g_v + ((size_t)b * NKV + kvh) * SEQ * HD;
    float* Pw = Ps + w * 16 * PP;

    for (int kt = 0; kt < SEQ / 64; kt++) {
        __syncthreads();
        const float* Kt = Kg + (size_t)kt * 64 * HD;
        const float* Vt = Vg + (size_t)kt * 64 * HD;
        #pragma unroll
        for (int it = 0; it < 16; it++) {
            int i = tid + it * 128;
            int r = i >> 5, c4 = (i & 31) << 2;
            float4 kv4 = *(const float4*)&Kt[r * HD + c4];
            float4 vv4 = *(const float4*)&Vt[r * HD + c4];
            kv4.x = f2t(kv4.x); kv4.y = f2t(kv4.y);
            kv4.z = f2t(kv4.z); kv4.w = f2t(kv4.w);
            vv4.x = f2t(vv4.x); vv4.y = f2t(vv4.y);
            vv4.z = f2t(vv4.z); vv4.w = f2t(vv4.w);
            *(float4*)&Ks[r * KP + c4] = kv4;
            *(float4*)&Vs[r * VP + c4] = vv4;
        }
        __syncthreads();

        float s[8][4] = {};
        #pragma unroll
        for (int ks = 0; ks < 16; ks++) {
            #pragma unroll
            for (int j = 0; j < 8; j++) {
                unsigned b2[2];
                b2[0] = __float_as_uint(Ks[(j * 8 + gid) * KP + ks * 8 + tig]);
                b2[1] = __float_as_uint(Ks[(j * 8 + gid) * KP + ks * 8 + tig + 4]);
                mma_tf32(s[j], QA[ks], b2);
            }
        }

        #pragma unroll
        for (int rr = 0; rr < 2; rr++) {
            float mx = -1e30f;
            #pragma unroll
            for (int j = 0; j < 8; j++)
                mx = fmaxf(mx, fmaxf(s[j][2 * rr], s[j][2 * rr + 1]));
            mx = fmaxf(mx, __shfl_xor_sync(0xffffffffu, mx, 1));
            mx = fmaxf(mx, __shfl_xor_sync(0xffffffffu, mx, 2));
            float mnew = fmaxf(mo[rr], mx);
            float corr = __expf(mo[rr] - mnew);
            float rs = 0.f;
            #pragma unroll
            for (int j = 0; j < 8; j++) {
                float p0 = f2t(__expf(s[j][2 * rr] - mnew));
                float p1 = f2t(__expf(s[j][2 * rr + 1] - mnew));
                s[j][2 * rr] = p0; s[j][2 * rr + 1] = p1;
                rs += p0 + p1;
            }
            rs += __shfl_xor_sync(0xffffffffu, rs, 1);
            rs += __shfl_xor_sync(0xffffffffu, rs, 2);
            l[rr] = l[rr] * corr + rs;
            mo[rr] = mnew;
            #pragma unroll
            for (int n = 0; n < 16; n++) {
                o[n][2 * rr] *= corr; o[n][2 * rr + 1] *= corr;
            }
        }

        #pragma unroll
        for (int j = 0; j < 8; j++) {
            *(float2*)&Pw[gid * PP + j * 8 + 2 * tig] =
                make_float2(s[j][0], s[j][1]);
            *(float2*)&Pw[(gid + 8) * PP + j * 8 + 2 * tig] =
                make_float2(s[j][2], s[j][3]);
        }
        __syncwarp();

        #pragma unroll
        for (int kk = 0; kk < 8; kk++) {
            unsigned a[4];
            a[0] = __float_as_uint(Pw[gid * PP + kk * 8 + tig]);
            a[1] = __float_as_uint(Pw[(gid + 8) * PP + kk * 8 + tig]);
            a[2] = __float_as_uint(Pw[gid * PP + kk * 8 + tig + 4]);
            a[3] = __float_as_uint(Pw[(gid + 8) * PP + kk * 8 + tig + 4]);
            #pragma unroll
            for (int n = 0; n < 16; n++) {
                unsigned b2[2];
                b2[0] = __float_as_uint(Vs[(kk * 8 + tig) * VP + n * 8 + gid]);
                b2[1] = __float_as_uint(Vs[(kk * 8 + tig + 4) * VP + n * 8 + gid]);
                mma_tf32(o[n], a, b2);
            }
        }
    }

    int t0 = b * SEQ + qt * 64 + w * 16 + gid;
    int t1 = t0 + 8;
    size_t r0 = (size_t)g_slot[t0] * DMODEL + h * HD;
    size_t r1 = (size_t)g_slot[t1] * DMODEL + h * HD;
    float inv0 = 1.f / l[0], inv1 = 1.f / l[1];
    #pragma unroll
    for (int n = 0; n < 16; n++) {
        *(float2*)&g_attn2[r0 + n * 8 + 2 * tig] =
            make_float2(o[n][0] * inv0, o[n][1] * inv0);
        *(float2*)&g_attn2[r1 + n * 8 + 2 * tig] =
            make_float2(o[n][2] * inv1, o[n][3] * inv1);
    }
}

/* ---------------- output projection (split-A) ---------------- */
__global__ void __launch_bounds__(256, 1) proj_o_kernel(float* __restrict__ out)
{
    extern __shared__ float smem[];
    const int m = blockIdx.z;
    const int cnt = g_cnt[m];
    const int row0 = blockIdx.y * BM, col0 = blockIdx.x * BN;
    if (row0 >= cnt) return;
    float acc[4][8][4] = {};
    gemm256_splitA(g_attn2 + (size_t)m * R_TOK * DMODEL, DMODEL,
                   g_wot + (size_t)m * DMODEL * DMODEL, DMODEL,
                   DMODEL, row0, col0, acc, smem);

    const int lane = threadIdx.x & 31, w = threadIdx.x >> 5;
    const int wm = (w >> 2) * 64, wn = (w & 3) * 64;
    const int gid = lane >> 2, tig = lane & 3;
    #pragma unroll
    for (int i = 0; i < 4; i++) {
        #pragma unroll
        for (int half = 0; half < 2; half++) {
            int r = row0 + wm + i * 16 + gid + half * 8;
            if (r >= cnt) continue;
            int tok = g_tok[m * R_TOK + r];
            #pragma unroll
            for (int j = 0; j < 8; j++) {
                int c = col0 + wn + j * 8 + tig * 2;
                out[(size_t)tok * DMODEL + c]     = acc[i][j][half * 2 + 0];
                out[(size_t)tok * DMODEL + c + 1] = acc[i][j][half * 2 + 1];
            }
        }
    }
}

/* ---------------- launch ---------------- */
extern "C" void kernel_launch(void* const* d_in, const int* in_sizes, int n_in,
                              void* d_out, int out_size) {
    (void)in_sizes; (void)n_in; (void)out_size;
    const float* x  = (const float*)d_in[0];
    const float* fc = (const float*)d_in[1];
    const float* Wq = (const float*)d_in[2];
    const float* Wk = (const float*)d_in[3];
    const float* Wv = (const float*)d_in[4];
    const float* Wo = (const float*)d_in[5];
    const int*   mid = (const int*)d_in[6];
    float* out = (float*)d_out;

    static int attr_done = 0;
    if (!attr_done) {
        cudaFuncSetAttribute(proj_q_kernel,
            cudaFuncAttributeMaxDynamicSharedMemorySize, GEMM_SMEM_BYTES);
        cudaFuncSetAttribute(proj_kv_kernel,
            cudaFuncAttributeMaxDynamicSharedMemorySize, GEMM_SMEM_BYTES);
        cudaFuncSetAttribute(proj_o_kernel,
            cudaFuncAttributeMaxDynamicSharedMemorySize, GEMM_SMEM_BYTES);
        cudaFuncSetAttribute(attn_kernel,
            cudaFuncAttributeMaxDynamicSharedMemorySize, ATTN_SMEM);
        attr_done = 1;
    }

    zero_cnt_kernel<<<1, 32>>>();
    assign_kernel<<<R_TOK / 256, 256>>>(mid);
    gather_x_kernel<<<R_TOK, 256>>>(x);
    pad_kernel<<<dim3(BM, NMOD), 256>>>();
    prep_kernel<<<4096, 256>>>(Wq, Wo);
    wsum_kernel<<<2048, 256>>>(Wk, Wv);
    proj_q_kernel<<<dim3(DMODEL / BN, R_TOK / BM, NMOD), 256, GEMM_SMEM_BYTES>>>(fc);
    proj_kv_kernel<<<dim3((2 * KVE) / BN, R_TOK / BM, NMOD), 256, GEMM_SMEM_BYTES>>>(fc);
    attn_kernel<<<dim3(SEQ / 64, NH, BDIM), 128, ATTN_SMEM>>>();
    proj_o_kernel<<<dim3(DMODEL / BN, R_TOK / BM, NMOD), 256, GEMM_SMEM_BYTES>>>(out);
}

// round 6
// speedup vs baseline: 1.1714x; 1.1714x over previous
#include <cuda_runtime.h>
#include <math.h>

#define BDIM 2
#define SEQ 2048
#define DMODEL 2048
#define NH 16
#define NKV 4
#define HD 128
#define NMOD 2
#define R_TOK (BDIM*SEQ)
#define KVE (NKV*HD)

/* GEMM tiling (round-4 proven config): CTA 128x128, 2 CTA/SM */
#define BM 128
#define BN 128
#define BK 16
#define AP 20
#define BP 136
#define GEMM_SMEM_FLOATS (2*BM*AP + 2*BK*BP)

/* ---------------- scratch ---------------- */
__device__ int   g_cnt[NMOD];
__device__ int   g_tok[NMOD*R_TOK];
__device__ int   g_slot[R_TOK];
__device__ float g_wk[NMOD*DMODEL*KVE];
__device__ float g_wv[NMOD*DMODEL*KVE];
__device__ float g_xt[(size_t)NMOD*R_TOK*DMODEL];
__device__ float g_wqt[(size_t)NMOD*DMODEL*DMODEL];
__device__ float g_wot[(size_t)NMOD*DMODEL*DMODEL];
__device__ float g_q[(size_t)BDIM*NH*SEQ*HD];
__device__ float g_k[(size_t)BDIM*NKV*SEQ*HD];
__device__ float g_v[(size_t)BDIM*NKV*SEQ*HD];
__device__ float g_attn2[(size_t)NMOD*R_TOK*DMODEL];

/* ---------------- helpers ---------------- */
__device__ __forceinline__ float f2t(float f) {
    unsigned u;
    asm("cvt.rna.tf32.f32 %0, %1;" : "=r"(u) : "f"(f));
    return __uint_as_float(u);
}
__device__ __forceinline__ unsigned f2tu(float f) {
    unsigned u;
    asm("cvt.rna.tf32.f32 %0, %1;" : "=r"(u) : "f"(f));
    return u;
}
__device__ __forceinline__ void mma_tf32(float* d, const unsigned* a, const unsigned* b) {
    asm volatile(
        "mma.sync.aligned.m16n8k8.row.col.f32.tf32.tf32.f32 "
        "{%0,%1,%2,%3},{%4,%5,%6,%7},{%8,%9},{%0,%1,%2,%3};"
        : "+f"(d[0]), "+f"(d[1]), "+f"(d[2]), "+f"(d[3])
        : "r"(a[0]), "r"(a[1]), "r"(a[2]), "r"(a[3]), "r"(b[0]), "r"(b[1]));
}

#define CP16(dst, src) \
    asm volatile("cp.async.cg.shared.global [%0], [%1], 16;" :: "r"(dst), "l"(src))
#define CP_COMMIT() asm volatile("cp.async.commit_group;")
#define CP_WAIT(n)  asm volatile("cp.async.wait_group %0;" :: "n"(n))

/* ---------------- modality gather machinery ---------------- */
__global__ void zero_cnt_kernel() {
    if (threadIdx.x < NMOD) g_cnt[threadIdx.x] = 0;
}
__global__ void assign_kernel(const int* __restrict__ mid) {
    int t = blockIdx.x * blockDim.x + threadIdx.x;
    if (t < R_TOK) {
        int m = mid[t];
        int s = atomicAdd(&g_cnt[m], 1);
        g_tok[m * R_TOK + s] = t;
        g_slot[t] = m * R_TOK + s;
    }
}
__global__ void gather_x_kernel(const float* __restrict__ x) {
    int t = blockIdx.x;
    int dst = g_slot[t];
    const float4* src = (const float4*)(x + (size_t)t * DMODEL);
    float4* d = (float4*)(g_xt + (size_t)dst * DMODEL);
    for (int i = threadIdx.x; i < DMODEL / 4; i += blockDim.x) {
        float4 v = src[i];
        v.x = f2t(v.x); v.y = f2t(v.y); v.z = f2t(v.z); v.w = f2t(v.w);
        d[i] = v;
    }
}
__global__ void pad_kernel() {
    int m = blockIdx.y;
    int cnt = g_cnt[m];
    int ru = (cnt + BM - 1) & ~(BM - 1);
    int r = cnt + blockIdx.x;
    if (r >= ru) return;
    float4* a = (float4*)(g_xt + ((size_t)m * R_TOK + r) * DMODEL);
    float4* b = (float4*)(g_attn2 + ((size_t)m * R_TOK + r) * DMODEL);
    float4 z = make_float4(0.f, 0.f, 0.f, 0.f);
    for (int i = threadIdx.x; i < DMODEL / 4; i += blockDim.x) { a[i] = z; b[i] = z; }
}

/* ---------------- prepass ---------------- */
__global__ void prep_kernel(const float* __restrict__ Wq,
                            const float* __restrict__ Wo) {
    const int NE = NMOD * DMODEL * DMODEL;
    for (int i = blockIdx.x * blockDim.x + threadIdx.x; i < 2 * NE;
         i += gridDim.x * blockDim.x) {
        if (i < NE) g_wqt[i]      = f2t(Wq[i]);
        else        g_wot[i - NE] = f2t(Wo[i - NE]);
    }
}
__global__ void wsum_kernel(const float* __restrict__ Wk,
                            const float* __restrict__ Wv) {
    const int n = NMOD * DMODEL * KVE;
    const int half = DMODEL * KVE;
    for (int i = blockIdx.x * blockDim.x + threadIdx.x; i < n;
         i += gridDim.x * blockDim.x) {
        int m = i / half;
        int rest = i - m * half;
        size_t base = (size_t)m * 2 * half + rest;
        g_wk[i] = f2t(Wk[base] + Wk[base + half]);
        g_wv[i] = f2t(Wv[base] + Wv[base + half]);
    }
}

/* ---------------- tf32 GEMM staging (round-4 config) ---------------- */
#define GEMM_STAGE_PROLOGUE()                                                 \
    const int tid = threadIdx.x;                                              \
    const int lane = tid & 31, w = tid >> 5;                                  \
    const int wm = (w >> 2) * 64, wn = (w & 3) * 32;                          \
    const int gid = lane >> 2, tig = lane & 3;                                \
    float* As = smem;                                                         \
    float* Bs = smem + 2 * BM * AP;                                           \
    const unsigned sA = (unsigned)__cvta_generic_to_shared(As);               \
    const unsigned sB = (unsigned)__cvta_generic_to_shared(Bs);               \
    auto issue = [&](int buf, int k0) {                                       \
        unsigned aBase = sA + (unsigned)buf * (BM * AP * 4);                  \
        unsigned bBase = sB + (unsigned)buf * (BK * BP * 4);                  \
        for (int q = 0; q < 2; q++) {                                         \
            int fa = tid + q * 256;                                           \
            CP16(aBase + ((fa >> 2) * AP + (fa & 3) * 4) * 4,                 \
                 &X[(size_t)(row0 + (fa >> 2)) * ldx + k0 + (fa & 3) * 4]);   \
            CP16(bBase + ((fa >> 5) * BP + (fa & 31) * 4) * 4,                \
                 &W[(size_t)(k0 + (fa >> 5)) * ldw + col0 + (fa & 31) * 4]);  \
        }                                                                     \
        CP_COMMIT();                                                          \
    };

__device__ __forceinline__ void gemm_tf32(
    const float* __restrict__ X, int ldx,
    const float* __restrict__ W, int ldw,
    int Kdim, int row0, int col0,
    float (&acc)[4][4][4], float* smem)
{
    GEMM_STAGE_PROLOGUE();
    issue(0, 0);
    const int T = Kdim / BK;
    for (int t = 0; t < T; t++) {
        const int buf = t & 1;
        if (t + 1 < T) { issue(buf ^ 1, (t + 1) * BK); CP_WAIT(1); }
        else           { CP_WAIT(0); }
        __syncthreads();
        const float* Ab = As + buf * (BM * AP);
        const float* Bb = Bs + buf * (BK * BP);
        #pragma unroll
        for (int kb = 0; kb < BK; kb += 8) {
            unsigned a[4][4], b[4][2];
            #pragma unroll
            for (int i = 0; i < 4; i++) {
                const float* ap = &Ab[(wm + i * 16 + gid) * AP + kb + tig];
                a[i][0] = __float_as_uint(ap[0]);
                a[i][1] = __float_as_uint(ap[8 * AP]);
                a[i][2] = __float_as_uint(ap[4]);
                a[i][3] = __float_as_uint(ap[8 * AP + 4]);
            }
            #pragma unroll
            for (int j = 0; j < 4; j++) {
                const float* bp = &Bb[(kb + tig) * BP + wn + j * 8 + gid];
                b[j][0] = __float_as_uint(bp[0]);
                b[j][1] = __float_as_uint(bp[4 * BP]);
            }
            #pragma unroll
            for (int i = 0; i < 4; i++)
                #pragma unroll
                for (int j = 0; j < 4; j++)
                    mma_tf32(acc[i][j], a[i], b[j]);
        }
        __syncthreads();
    }
}

__device__ __forceinline__ void gemm_tf32_splitA(
    const float* __restrict__ X, int ldx,
    const float* __restrict__ W, int ldw,
    int Kdim, int row0, int col0,
    float (&acc)[4][4][4], float* smem)
{
    GEMM_STAGE_PROLOGUE();
    issue(0, 0);
    const int T = Kdim / BK;
    for (int t = 0; t < T; t++) {
        const int buf = t & 1;
        if (t + 1 < T) { issue(buf ^ 1, (t + 1) * BK); CP_WAIT(1); }
        else           { CP_WAIT(0); }
        __syncthreads();
        const float* Ab = As + buf * (BM * AP);
        const float* Bb = Bs + buf * (BK * BP);
        #pragma unroll
        for (int kb = 0; kb < BK; kb += 8) {
            unsigned b[4][2];
            #pragma unroll
            for (int j = 0; j < 4; j++) {
                const float* bp = &Bb[(kb + tig) * BP + wn + j * 8 + gid];
                b[j][0] = __float_as_uint(bp[0]);
                b[j][1] = __float_as_uint(bp[4 * BP]);
            }
            #pragma unroll
            for (int i = 0; i < 4; i++) {
                const float* ap = &Ab[(wm + i * 16 + gid) * AP + kb + tig];
                float v[4] = {ap[0], ap[8 * AP], ap[4], ap[8 * AP + 4]};
                unsigned ah[4], al[4];
                #pragma unroll
                for (int q = 0; q < 4; q++) {
                    ah[q] = f2tu(v[q]);
                    al[q] = f2tu(v[q] - __uint_as_float(ah[q]));
                }
                #pragma unroll
                for (int j = 0; j < 4; j++) {
                    mma_tf32(acc[i][j], ah, b[j]);
                    mma_tf32(acc[i][j], al, b[j]);
                }
            }
        }
        __syncthreads();
    }
}

/* ---------------- Q projection + RoPE ---------------- */
__global__ void __launch_bounds__(256, 2) proj_q_kernel(
    const float* __restrict__ fc)
{
    __shared__ float smem[GEMM_SMEM_FLOATS];
    const int m = blockIdx.z;
    const int cnt = g_cnt[m];
    const int row0 = blockIdx.y * BM, col0 = blockIdx.x * BN;
    if (row0 >= cnt) return;
    float acc[4][4][4] = {};
    gemm_tf32(g_xt + (size_t)m * R_TOK * DMODEL, DMODEL,
              g_wqt + (size_t)m * DMODEL * DMODEL, DMODEL,
              DMODEL, row0, col0, acc, smem);

    const int lane = threadIdx.x & 31, w = threadIdx.x >> 5;
    const int wm = (w >> 2) * 64, wn = (w & 3) * 32;
    const int gid = lane >> 2, tig = lane & 3;
    #pragma unroll
    for (int i = 0; i < 4; i++) {
        #pragma unroll
        for (int half = 0; half < 2; half++) {
            int r = row0 + wm + i * 16 + gid + half * 8;
            if (r >= cnt) continue;
            int tok = g_tok[m * R_TOK + r];
            int b_ = tok >> 11, s = tok & (SEQ - 1);
            #pragma unroll
            for (int j = 0; j < 4; j++) {
                int c = col0 + wn + j * 8 + tig * 2;
                float e = acc[i][j][half * 2 + 0];
                float o = acc[i][j][half * 2 + 1];
                int h = c >> 7, d = c & 127, pr = d >> 1;
                float cv = fc[(size_t)s * 256 + pr * 4 + 0];
                float sv = fc[(size_t)s * 256 + pr * 4 + 2];
                size_t base = (((size_t)b_ * NH + h) * SEQ + s) * HD + d;
                g_q[base]     = e * cv + o * sv;
                g_q[base + 1] = o * cv - e * sv;
            }
        }
    }
}

/* ---------------- K/V projection (+RoPE on K) ---------------- */
__global__ void __launch_bounds__(256, 2) proj_kv_kernel(
    const float* __restrict__ fc)
{
    __shared__ float smem[GEMM_SMEM_FLOATS];
    const int m = blockIdx.z;
    const int cnt = g_cnt[m];
    const int row0 = blockIdx.y * BM;
    if (row0 >= cnt) return;
    const int n0 = blockIdx.x * BN;
    const bool isV = (n0 >= KVE);
    const float* W = (isV ? g_wv : g_wk) + (size_t)m * DMODEL * KVE;
    const int c0base = isV ? n0 - KVE : n0;

    float acc[4][4][4] = {};
    gemm_tf32(g_xt + (size_t)m * R_TOK * DMODEL, DMODEL,
              W, KVE, DMODEL, row0, c0base, acc, smem);

    const int lane = threadIdx.x & 31, w = threadIdx.x >> 5;
    const int wm = (w >> 2) * 64, wn = (w & 3) * 32;
    const int gid = lane >> 2, tig = lane & 3;
    #pragma unroll
    for (int i = 0; i < 4; i++) {
        #pragma unroll
        for (int half = 0; half < 2; half++) {
            int r = row0 + wm + i * 16 + gid + half * 8;
            if (r >= cnt) continue;
            int tok = g_tok[m * R_TOK + r];
            int b_ = tok >> 11, s = tok & (SEQ - 1);
            #pragma unroll
            for (int j = 0; j < 4; j++) {
                int c = c0base + wn + j * 8 + tig * 2;
                int kvh = c >> 7, d = c & 127;
                float e = acc[i][j][half * 2 + 0];
                float o = acc[i][j][half * 2 + 1];
                size_t base = (((size_t)b_ * NKV + kvh) * SEQ + s) * HD + d;
                if (!isV) {
                    int pr = d >> 1;
                    float cv = fc[(size_t)s * 256 + pr * 4 + 0];
                    float sv = fc[(size_t)s * 256 + pr * 4 + 2];
                    g_k[base]     = e * cv + o * sv;
                    g_k[base + 1] = o * cv - e * sv;
                } else {
                    g_v[base]     = e;
                    g_v[base + 1] = o;
                }
            }
        }
    }
}

/* ---------------- flash attention: 128 q-rows/CTA, 8 warps ---------------- */
#define KP 132
#define VP 136
#define PP 68
#define ATTN_SMEM ((64*KP + 64*VP + 128*PP) * 4)

__global__ void __launch_bounds__(256) attn_kernel() {
    extern __shared__ float sm[];
    float* Ks = sm;
    float* Vs = Ks + 64 * KP;
    float* Ps = Vs + 64 * VP;

    const int qt = blockIdx.x, h = blockIdx.y, b = blockIdx.z;
    const int kvh = h >> 2;
    const int tid = threadIdx.x;
    const int w = tid >> 5, lane = tid & 31, gid = lane >> 2, tig = lane & 3;
    const float scale = 0.08838834764831845f;

    /* each warp owns rows qt*128 + w*16 .. +16 */
    const float* Qg = g_q + (((size_t)b * NH + h) * SEQ + qt * 128 + w * 16) * HD;
    unsigned QA[16][4];
    #pragma unroll
    for (int ks = 0; ks < 16; ks++) {
        QA[ks][0] = f2tu(Qg[gid * HD + 8 * ks + tig] * scale);
        QA[ks][1] = f2tu(Qg[(gid + 8) * HD + 8 * ks + tig] * scale);
        QA[ks][2] = f2tu(Qg[gid * HD + 8 * ks + tig + 4] * scale);
        QA[ks][3] = f2tu(Qg[(gid + 8) * HD + 8 * ks + tig + 4] * scale);
    }

    float o[16][4];
    #pragma unroll
    for (int n = 0; n < 16; n++)
        #pragma unroll
        for (int q = 0; q < 4; q++) o[n][q] = 0.f;
    float mo[2] = {-1e30f, -1e30f}, l[2] = {0.f, 0.f};

    const float* Kg = g_k + ((size_t)b * NKV + kvh) * SEQ * HD;
    const float* Vg = g_v + ((size_t)b * NKV + kvh) * SEQ * HD;
    float* Pw = Ps + w * 16 * PP;

    for (int kt = 0; kt < SEQ / 64; kt++) {
        __syncthreads();
        const float* Kt = Kg + (size_t)kt * 64 * HD;
        const float* Vt = Vg + (size_t)kt * 64 * HD;
        /* 64x128 K + V tiles, 256 threads, float4: 8 iters */
        #pragma unroll
        for (int it = 0; it < 8; it++) {
            int i = tid + it * 256;
            int r = i >> 5, c4 = (i & 31) << 2;
            float4 kv4 = *(const float4*)&Kt[r * HD + c4];
            float4 vv4 = *(const float4*)&Vt[r * HD + c4];
            kv4.x = f2t(kv4.x); kv4.y = f2t(kv4.y);
            kv4.z = f2t(kv4.z); kv4.w = f2t(kv4.w);
            vv4.x = f2t(vv4.x); vv4.y = f2t(vv4.y);
            vv4.z = f2t(vv4.z); vv4.w = f2t(vv4.w);
            *(float4*)&Ks[r * KP + c4] = kv4;
            *(float4*)&Vs[r * VP + c4] = vv4;
        }
        __syncthreads();

        float s[8][4] = {};
        #pragma unroll
        for (int ks = 0; ks < 16; ks++) {
            #pragma unroll
            for (int j = 0; j < 8; j++) {
                unsigned b2[2];
                b2[0] = __float_as_uint(Ks[(j * 8 + gid) * KP + ks * 8 + tig]);
                b2[1] = __float_as_uint(Ks[(j * 8 + gid) * KP + ks * 8 + tig + 4]);
                mma_tf32(s[j], QA[ks], b2);
            }
        }

        #pragma unroll
        for (int rr = 0; rr < 2; rr++) {
            float mx = -1e30f;
            #pragma unroll
            for (int j = 0; j < 8; j++)
                mx = fmaxf(mx, fmaxf(s[j][2 * rr], s[j][2 * rr + 1]));
            mx = fmaxf(mx, __shfl_xor_sync(0xffffffffu, mx, 1));
            mx = fmaxf(mx, __shfl_xor_sync(0xffffffffu, mx, 2));
            float mnew = fmaxf(mo[rr], mx);
            float corr = __expf(mo[rr] - mnew);
            float rs = 0.f;
            #pragma unroll
            for (int j = 0; j < 8; j++) {
                float p0 = f2t(__expf(s[j][2 * rr] - mnew));
                float p1 = f2t(__expf(s[j][2 * rr + 1] - mnew));
                s[j][2 * rr] = p0; s[j][2 * rr + 1] = p1;
                rs += p0 + p1;
            }
            rs += __shfl_xor_sync(0xffffffffu, rs, 1);
            rs += __shfl_xor_sync(0xffffffffu, rs, 2);
            l[rr] = l[rr] * corr + rs;
            mo[rr] = mnew;
            #pragma unroll
            for (int n = 0; n < 16; n++) {
                o[n][2 * rr] *= corr; o[n][2 * rr + 1] *= corr;
            }
        }

        #pragma unroll
        for (int j = 0; j < 8; j++) {
            *(float2*)&Pw[gid * PP + j * 8 + 2 * tig] =
                make_float2(s[j][0], s[j][1]);
            *(float2*)&Pw[(gid + 8) * PP + j * 8 + 2 * tig] =
                make_float2(s[j][2], s[j][3]);
        }
        __syncwarp();

        #pragma unroll
        for (int kk = 0; kk < 8; kk++) {
            unsigned a[4];
            a[0] = __float_as_uint(Pw[gid * PP + kk * 8 + tig]);
            a[1] = __float_as_uint(Pw[(gid + 8) * PP + kk * 8 + tig]);
            a[2] = __float_as_uint(Pw[gid * PP + kk * 8 + tig + 4]);
            a[3] = __float_as_uint(Pw[(gid + 8) * PP + kk * 8 + tig + 4]);
            #pragma unroll
            for (int n = 0; n < 16; n++) {
                unsigned b2[2];
                b2[0] = __float_as_uint(Vs[(kk * 8 + tig) * VP + n * 8 + gid]);
                b2[1] = __float_as_uint(Vs[(kk * 8 + tig + 4) * VP + n * 8 + gid]);
                mma_tf32(o[n], a, b2);
            }
        }
    }

    int t0 = b * SEQ + qt * 128 + w * 16 + gid;
    int t1 = t0 + 8;
    size_t r0 = (size_t)g_slot[t0] * DMODEL + h * HD;
    size_t r1 = (size_t)g_slot[t1] * DMODEL + h * HD;
    float inv0 = 1.f / l[0], inv1 = 1.f / l[1];
    #pragma unroll
    for (int n = 0; n < 16; n++) {
        *(float2*)&g_attn2[r0 + n * 8 + 2 * tig] =
            make_float2(o[n][0] * inv0, o[n][1] * inv0);
        *(float2*)&g_attn2[r1 + n * 8 + 2 * tig] =
            make_float2(o[n][2] * inv1, o[n][3] * inv1);
    }
}

/* ---------------- output projection (split-A) ---------------- */
__global__ void __launch_bounds__(256, 2) proj_o_kernel(float* __restrict__ out)
{
    __shared__ float smem[GEMM_SMEM_FLOATS];
    const int m = blockIdx.z;
    const int cnt = g_cnt[m];
    const int row0 = blockIdx.y * BM, col0 = blockIdx.x * BN;
    if (row0 >= cnt) return;
    float acc[4][4][4] = {};
    gemm_tf32_splitA(g_attn2 + (size_t)m * R_TOK * DMODEL, DMODEL,
                     g_wot + (size_t)m * DMODEL * DMODEL, DMODEL,
                     DMODEL, row0, col0, acc, smem);

    const int lane = threadIdx.x & 31, w = threadIdx.x >> 5;
    const int wm = (w >> 2) * 64, wn = (w & 3) * 32;
    const int gid = lane >> 2, tig = lane & 3;
    #pragma unroll
    for (int i = 0; i < 4; i++) {
        #pragma unroll
        for (int half = 0; half < 2; half++) {
            int r = row0 + wm + i * 16 + gid + half * 8;
            if (r >= cnt) continue;
            int tok = g_tok[m * R_TOK + r];
            #pragma unroll
            for (int j = 0; j < 4; j++) {
                int c = col0 + wn + j * 8 + tig * 2;
                out[(size_t)tok * DMODEL + c]     = acc[i][j][half * 2 + 0];
                out[(size_t)tok * DMODEL + c + 1] = acc[i][j][half * 2 + 1];
            }
        }
    }
}

/* ---------------- launch ---------------- */
extern "C" void kernel_launch(void* const* d_in, const int* in_sizes, int n_in,
                              void* d_out, int out_size) {
    (void)in_sizes; (void)n_in; (void)out_size;
    const float* x  = (const float*)d_in[0];
    const float* fc = (const float*)d_in[1];
    const float* Wq = (const float*)d_in[2];
    const float* Wk = (const float*)d_in[3];
    const float* Wv = (const float*)d_in[4];
    const float* Wo = (const float*)d_in[5];
    const int*   mid = (const int*)d_in[6];
    float* out = (float*)d_out;

    static int attr_done = 0;
    if (!attr_done) {
        cudaFuncSetAttribute(attn_kernel,
            cudaFuncAttributeMaxDynamicSharedMemorySize, ATTN_SMEM);
        attr_done = 1;
    }

    zero_cnt_kernel<<<1, 32>>>();
    assign_kernel<<<R_TOK / 256, 256>>>(mid);
    gather_x_kernel<<<R_TOK, 256>>>(x);
    pad_kernel<<<dim3(BM, NMOD), 256>>>();
    prep_kernel<<<4096, 256>>>(Wq, Wo);
    wsum_kernel<<<2048, 256>>>(Wk, Wv);
    proj_q_kernel<<<dim3(DMODEL / BN, R_TOK / BM, NMOD), 256>>>(fc);
    proj_kv_kernel<<<dim3((2 * KVE) / BN, R_TOK / BM, NMOD), 256>>>(fc);
    attn_kernel<<<dim3(SEQ / 128, NH, BDIM), 256, ATTN_SMEM>>>();
    proj_o_kernel<<<dim3(DMODEL / BN, R_TOK / BM, NMOD), 256>>>(out);
}

// round 7
// speedup vs baseline: 1.2326x; 1.0523x over previous
#include <cuda_runtime.h>
#include <cuda_bf16.h>
#include <math.h>

#define BDIM 2
#define SEQ 2048
#define DMODEL 2048
#define NH 16
#define NKV 4
#define HD 128
#define NMOD 2
#define R_TOK (BDIM*SEQ)
#define KVE (NKV*HD)

/* tf32 GEMM tiling (proven): CTA 128x128, 2 CTA/SM */
#define BM 128
#define BN 128
#define BK 16
#define AP 20
#define BP 136
#define GEMM_SMEM_FLOATS (2*BM*AP + 2*BK*BP)

/* ---------------- scratch ---------------- */
__device__ int   g_cnt[NMOD];
__device__ int   g_tok[NMOD*R_TOK];
__device__ int   g_slot[R_TOK];
__device__ float g_wk[NMOD*DMODEL*KVE];
__device__ float g_wv[NMOD*DMODEL*KVE];
__device__ float g_xt[(size_t)NMOD*R_TOK*DMODEL];
__device__ float g_wqt[(size_t)NMOD*DMODEL*DMODEL];
/* Wo as bf16 hi/lo, k-pair interleaved: [m][k/2][n], uint = bf16(k)|bf16(k+1)<<16 */
__device__ unsigned g_woh[(size_t)NMOD*(DMODEL/2)*DMODEL];
__device__ unsigned g_wol[(size_t)NMOD*(DMODEL/2)*DMODEL];
__device__ float g_q[(size_t)BDIM*NH*SEQ*HD];
__device__ float g_k[(size_t)BDIM*NKV*SEQ*HD];
__device__ float g_v[(size_t)BDIM*NKV*SEQ*HD];
/* attention output in slot order, split bf16 hi/lo */
__device__ __nv_bfloat16 g_aoh[(size_t)NMOD*R_TOK*DMODEL];
__device__ __nv_bfloat16 g_aol[(size_t)NMOD*R_TOK*DMODEL];

/* ---------------- helpers ---------------- */
__device__ __forceinline__ float f2t(float f) {
    unsigned u;
    asm("cvt.rna.tf32.f32 %0, %1;" : "=r"(u) : "f"(f));
    return __uint_as_float(u);
}
__device__ __forceinline__ unsigned f2tu(float f) {
    unsigned u;
    asm("cvt.rna.tf32.f32 %0, %1;" : "=r"(u) : "f"(f));
    return u;
}
__device__ __forceinline__ void mma_tf32(float* d, const unsigned* a, const unsigned* b) {
    asm volatile(
        "mma.sync.aligned.m16n8k8.row.col.f32.tf32.tf32.f32 "
        "{%0,%1,%2,%3},{%4,%5,%6,%7},{%8,%9},{%0,%1,%2,%3};"
        : "+f"(d[0]), "+f"(d[1]), "+f"(d[2]), "+f"(d[3])
        : "r"(a[0]), "r"(a[1]), "r"(a[2]), "r"(a[3]), "r"(b[0]), "r"(b[1]));
}
__device__ __forceinline__ void mma_bf16(float* d, const unsigned* a, const unsigned* b) {
    asm volatile(
        "mma.sync.aligned.m16n8k16.row.col.f32.bf16.bf16.f32 "
        "{%0,%1,%2,%3},{%4,%5,%6,%7},{%8,%9},{%0,%1,%2,%3};"
        : "+f"(d[0]), "+f"(d[1]), "+f"(d[2]), "+f"(d[3])
        : "r"(a[0]), "r"(a[1]), "r"(a[2]), "r"(a[3]), "r"(b[0]), "r"(b[1]));
}
__device__ __forceinline__ unsigned pk2bf(float a, float b) {
    return (unsigned)__bfloat16_as_ushort(__float2bfloat16(a)) |
           ((unsigned)__bfloat16_as_ushort(__float2bfloat16(b)) << 16);
}
__device__ __forceinline__ float bfres(float v) {   /* v - bf16(v) */
    return v - __bfloat162float(__float2bfloat16(v));
}

#define CP16(dst, src) \
    asm volatile("cp.async.cg.shared.global [%0], [%1], 16;" :: "r"(dst), "l"(src))
#define CP_COMMIT() asm volatile("cp.async.commit_group;")
#define CP_WAIT(n)  asm volatile("cp.async.wait_group %0;" :: "n"(n))

/* ---------------- modality gather machinery ---------------- */
__global__ void zero_cnt_kernel() {
    if (threadIdx.x < NMOD) g_cnt[threadIdx.x] = 0;
}
__global__ void assign_kernel(const int* __restrict__ mid) {
    int t = blockIdx.x * blockDim.x + threadIdx.x;
    if (t < R_TOK) {
        int m = mid[t];
        int s = atomicAdd(&g_cnt[m], 1);
        g_tok[m * R_TOK + s] = t;
        g_slot[t] = m * R_TOK + s;
    }
}
__global__ void gather_x_kernel(const float* __restrict__ x) {
    int t = blockIdx.x;
    int dst = g_slot[t];
    const float4* src = (const float4*)(x + (size_t)t * DMODEL);
    float4* d = (float4*)(g_xt + (size_t)dst * DMODEL);
    for (int i = threadIdx.x; i < DMODEL / 4; i += blockDim.x) {
        float4 v = src[i];
        v.x = f2t(v.x); v.y = f2t(v.y); v.z = f2t(v.z); v.w = f2t(v.w);
        d[i] = v;
    }
}
__global__ void pad_kernel() {
    int m = blockIdx.y;
    int cnt = g_cnt[m];
    int ru = (cnt + BM - 1) & ~(BM - 1);
    int r = cnt + blockIdx.x;
    if (r >= ru) return;
    size_t rowe = ((size_t)m * R_TOK + r) * DMODEL;
    float4* a = (float4*)(g_xt + rowe);
    float4 z = make_float4(0.f, 0.f, 0.f, 0.f);
    for (int i = threadIdx.x; i < DMODEL / 4; i += blockDim.x) a[i] = z;
    uint4* hh = (uint4*)(g_aoh + rowe);
    uint4* ll = (uint4*)(g_aol + rowe);
    uint4 uz = make_uint4(0, 0, 0, 0);
    for (int i = threadIdx.x; i < DMODEL / 8; i += blockDim.x) { hh[i] = uz; ll[i] = uz; }
}

/* ---------------- prepass: tf32 Wq; bf16 hi/lo k-pair Wo ---------------- */
__global__ void prep_kernel(const float* __restrict__ Wq,
                            const float* __restrict__ Wo) {
    const int NE = NMOD * DMODEL * DMODEL;           /* Wq elems */
    const int NP = NMOD * (DMODEL / 2) * DMODEL;     /* Wo k-pairs */
    for (int i = blockIdx.x * blockDim.x + threadIdx.x; i < NE + NP;
         i += gridDim.x * blockDim.x) {
        if (i < NE) { g_wqt[i] = f2t(Wq[i]); continue; }
        int j = i - NE;
        int n = j & (DMODEL - 1);
        int rest = j >> 11;
        int k2 = rest & (DMODEL / 2 - 1);
        int m = rest >> 10;
        size_t base = ((size_t)(m * DMODEL + 2 * k2)) * DMODEL + n;
        float w0 = Wo[base], w1 = Wo[base + DMODEL];
        g_woh[j] = pk2bf(w0, w1);
        g_wol[j] = pk2bf(bfres(w0), bfres(w1));
    }
}
__global__ void wsum_kernel(const float* __restrict__ Wk,
                            const float* __restrict__ Wv) {
    const int n = NMOD * DMODEL * KVE;
    const int half = DMODEL * KVE;
    for (int i = blockIdx.x * blockDim.x + threadIdx.x; i < n;
         i += gridDim.x * blockDim.x) {
        int m = i / half;
        int rest = i - m * half;
        size_t base = (size_t)m * 2 * half + rest;
        g_wk[i] = f2t(Wk[base] + Wk[base + half]);
        g_wv[i] = f2t(Wv[base] + Wv[base + half]);
    }
}

/* ---------------- tf32 GEMM (round-6 proven) ---------------- */
#define GEMM_STAGE_PROLOGUE()                                                 \
    const int tid = threadIdx.x;                                              \
    const int lane = tid & 31, w = tid >> 5;                                  \
    const int wm = (w >> 2) * 64, wn = (w & 3) * 32;                          \
    const int gid = lane >> 2, tig = lane & 3;                                \
    float* As = smem;                                                         \
    float* Bs = smem + 2 * BM * AP;                                           \
    const unsigned sA = (unsigned)__cvta_generic_to_shared(As);               \
    const unsigned sB = (unsigned)__cvta_generic_to_shared(Bs);               \
    auto issue = [&](int buf, int k0) {                                       \
        unsigned aBase = sA + (unsigned)buf * (BM * AP * 4);                  \
        unsigned bBase = sB + (unsigned)buf * (BK * BP * 4);                  \
        for (int q = 0; q < 2; q++) {                                         \
            int fa = tid + q * 256;                                           \
            CP16(aBase + ((fa >> 2) * AP + (fa & 3) * 4) * 4,                 \
                 &X[(size_t)(row0 + (fa >> 2)) * ldx + k0 + (fa & 3) * 4]);   \
            CP16(bBase + ((fa >> 5) * BP + (fa & 31) * 4) * 4,                \
                 &W[(size_t)(k0 + (fa >> 5)) * ldw + col0 + (fa & 31) * 4]);  \
        }                                                                     \
        CP_COMMIT();                                                          \
    };

__device__ __forceinline__ void gemm_tf32(
    const float* __restrict__ X, int ldx,
    const float* __restrict__ W, int ldw,
    int Kdim, int row0, int col0,
    float (&acc)[4][4][4], float* smem)
{
    GEMM_STAGE_PROLOGUE();
    issue(0, 0);
    const int T = Kdim / BK;
    for (int t = 0; t < T; t++) {
        const int buf = t & 1;
        if (t + 1 < T) { issue(buf ^ 1, (t + 1) * BK); CP_WAIT(1); }
        else           { CP_WAIT(0); }
        __syncthreads();
        const float* Ab = As + buf * (BM * AP);
        const float* Bb = Bs + buf * (BK * BP);
        #pragma unroll
        for (int kb = 0; kb < BK; kb += 8) {
            unsigned a[4][4], b[4][2];
            #pragma unroll
            for (int i = 0; i < 4; i++) {
                const float* ap = &Ab[(wm + i * 16 + gid) * AP + kb + tig];
                a[i][0] = __float_as_uint(ap[0]);
                a[i][1] = __float_as_uint(ap[8 * AP]);
                a[i][2] = __float_as_uint(ap[4]);
                a[i][3] = __float_as_uint(ap[8 * AP + 4]);
            }
            #pragma unroll
            for (int j = 0; j < 4; j++) {
                const float* bp = &Bb[(kb + tig) * BP + wn + j * 8 + gid];
                b[j][0] = __float_as_uint(bp[0]);
                b[j][1] = __float_as_uint(bp[4 * BP]);
            }
            #pragma unroll
            for (int i = 0; i < 4; i++)
                #pragma unroll
                for (int j = 0; j < 4; j++)
                    mma_tf32(acc[i][j], a[i], b[j]);
        }
        __syncthreads();
    }
}

/* ---------------- Q projection + RoPE ---------------- */
__global__ void __launch_bounds__(256, 2) proj_q_kernel(
    const float* __restrict__ fc)
{
    __shared__ float smem[GEMM_SMEM_FLOATS];
    const int m = blockIdx.z;
    const int cnt = g_cnt[m];
    const int row0 = blockIdx.y * BM, col0 = blockIdx.x * BN;
    if (row0 >= cnt) return;
    float acc[4][4][4] = {};
    gemm_tf32(g_xt + (size_t)m * R_TOK * DMODEL, DMODEL,
              g_wqt + (size_t)m * DMODEL * DMODEL, DMODEL,
              DMODEL, row0, col0, acc, smem);

    const int lane = threadIdx.x & 31, w = threadIdx.x >> 5;
    const int wm = (w >> 2) * 64, wn = (w & 3) * 32;
    const int gid = lane >> 2, tig = lane & 3;
    #pragma unroll
    for (int i = 0; i < 4; i++) {
        #pragma unroll
        for (int half = 0; half < 2; half++) {
            int r = row0 + wm + i * 16 + gid + half * 8;
            if (r >= cnt) continue;
            int tok = g_tok[m * R_TOK + r];
            int b_ = tok >> 11, s = tok & (SEQ - 1);
            #pragma unroll
            for (int j = 0; j < 4; j++) {
                int c = col0 + wn + j * 8 + tig * 2;
                float e = acc[i][j][half * 2 + 0];
                float o = acc[i][j][half * 2 + 1];
                int h = c >> 7, d = c & 127, pr = d >> 1;
                float cv = fc[(size_t)s * 256 + pr * 4 + 0];
                float sv = fc[(size_t)s * 256 + pr * 4 + 2];
                size_t base = (((size_t)b_ * NH + h) * SEQ + s) * HD + d;
                g_q[base]     = e * cv + o * sv;
                g_q[base + 1] = o * cv - e * sv;
            }
        }
    }
}

/* ---------------- K/V projection (+RoPE on K) ---------------- */
__global__ void __launch_bounds__(256, 2) proj_kv_kernel(
    const float* __restrict__ fc)
{
    __shared__ float smem[GEMM_SMEM_FLOATS];
    const int m = blockIdx.z;
    const int cnt = g_cnt[m];
    const int row0 = blockIdx.y * BM;
    if (row0 >= cnt) return;
    const int n0 = blockIdx.x * BN;
    const bool isV = (n0 >= KVE);
    const float* W = (isV ? g_wv : g_wk) + (size_t)m * DMODEL * KVE;
    const int c0base = isV ? n0 - KVE : n0;

    float acc[4][4][4] = {};
    gemm_tf32(g_xt + (size_t)m * R_TOK * DMODEL, DMODEL,
              W, KVE, DMODEL, row0, c0base, acc, smem);

    const int lane = threadIdx.x & 31, w = threadIdx.x >> 5;
    const int wm = (w >> 2) * 64, wn = (w & 3) * 32;
    const int gid = lane >> 2, tig = lane & 3;
    #pragma unroll
    for (int i = 0; i < 4; i++) {
        #pragma unroll
        for (int half = 0; half < 2; half++) {
            int r = row0 + wm + i * 16 + gid + half * 8;
            if (r >= cnt) continue;
            int tok = g_tok[m * R_TOK + r];
            int b_ = tok >> 11, s = tok & (SEQ - 1);
            #pragma unroll
            for (int j = 0; j < 4; j++) {
                int c = c0base + wn + j * 8 + tig * 2;
                int kvh = c >> 7, d = c & 127;
                float e = acc[i][j][half * 2 + 0];
                float o = acc[i][j][half * 2 + 1];
                size_t base = (((size_t)b_ * NKV + kvh) * SEQ + s) * HD + d;
                if (!isV) {
                    int pr = d >> 1;
                    float cv = fc[(size_t)s * 256 + pr * 4 + 0];
                    float sv = fc[(size_t)s * 256 + pr * 4 + 2];
                    g_k[base]     = e * cv + o * sv;
                    g_k[base + 1] = o * cv - e * sv;
                } else {
                    g_v[base]     = e;
                    g_v[base + 1] = o;
                }
            }
        }
    }
}

/* ---------------- flash attention: 128 q-rows/CTA, 8 warps ---------------- */
#define KP 132
#define VP 136
#define PP 68
#define ATTN_SMEM ((64*KP + 64*VP + 128*PP) * 4)

__global__ void __launch_bounds__(256) attn_kernel() {
    extern __shared__ float sm[];
    float* Ks = sm;
    float* Vs = Ks + 64 * KP;
    float* Ps = Vs + 64 * VP;

    const int qt = blockIdx.x, h = blockIdx.y, b = blockIdx.z;
    const int kvh = h >> 2;
    const int tid = threadIdx.x;
    const int w = tid >> 5, lane = tid & 31, gid = lane >> 2, tig = lane & 3;
    const float scale = 0.08838834764831845f;

    const float* Qg = g_q + (((size_t)b * NH + h) * SEQ + qt * 128 + w * 16) * HD;
    unsigned QA[16][4];
    #pragma unroll
    for (int ks = 0; ks < 16; ks++) {
        QA[ks][0] = f2tu(Qg[gid * HD + 8 * ks + tig] * scale);
        QA[ks][1] = f2tu(Qg[(gid + 8) * HD + 8 * ks + tig] * scale);
        QA[ks][2] = f2tu(Qg[gid * HD + 8 * ks + tig + 4] * scale);
        QA[ks][3] = f2tu(Qg[(gid + 8) * HD + 8 * ks + tig + 4] * scale);
    }

    float o[16][4];
    #pragma unroll
    for (int n = 0; n < 16; n++)
        #pragma unroll
        for (int q = 0; q < 4; q++) o[n][q] = 0.f;
    float mo[2] = {-1e30f, -1e30f}, l[2] = {0.f, 0.f};

    const float* Kg = g_k + ((size_t)b * NKV + kvh) * SEQ * HD;
    const float* Vg = g_v + ((size_t)b * NKV + kvh) * SEQ * HD;
    float* Pw = Ps + w * 16 * PP;

    for (int kt = 0; kt < SEQ / 64; kt++) {
        __syncthreads();
        const float* Kt = Kg + (size_t)kt * 64 * HD;
        const float* Vt = Vg + (size_t)kt * 64 * HD;
        #pragma unroll
        for (int it = 0; it < 8; it++) {
            int i = tid + it * 256;
            int r = i >> 5, c4 = (i & 31) << 2;
            float4 kv4 = *(const float4*)&Kt[r * HD + c4];
            float4 vv4 = *(const float4*)&Vt[r * HD + c4];
            kv4.x = f2t(kv4.x); kv4.y = f2t(kv4.y);
            kv4.z = f2t(kv4.z); kv4.w = f2t(kv4.w);
            vv4.x = f2t(vv4.x); vv4.y = f2t(vv4.y);
            vv4.z = f2t(vv4.z); vv4.w = f2t(vv4.w);
            *(float4*)&Ks[r * KP + c4] = kv4;
            *(float4*)&Vs[r * VP + c4] = vv4;
        }
        __syncthreads();

        float s[8][4] = {};
        #pragma unroll
        for (int ks = 0; ks < 16; ks++) {
            #pragma unroll
            for (int j = 0; j < 8; j++) {
                unsigned b2[2];
                b2[0] = __float_as_uint(Ks[(j * 8 + gid) * KP + ks * 8 + tig]);
                b2[1] = __float_as_uint(Ks[(j * 8 + gid) * KP + ks * 8 + tig + 4]);
                mma_tf32(s[j], QA[ks], b2);
            }
        }

        #pragma unroll
        for (int rr = 0; rr < 2; rr++) {
            float mx = -1e30f;
            #pragma unroll
            for (int j = 0; j < 8; j++)
                mx = fmaxf(mx, fmaxf(s[j][2 * rr], s[j][2 * rr + 1]));
            mx = fmaxf(mx, __shfl_xor_sync(0xffffffffu, mx, 1));
            mx = fmaxf(mx, __shfl_xor_sync(0xffffffffu, mx, 2));
            float mnew = fmaxf(mo[rr], mx);
            float corr = __expf(mo[rr] - mnew);
            float rs = 0.f;
            #pragma unroll
            for (int j = 0; j < 8; j++) {
                float p0 = f2t(__expf(s[j][2 * rr] - mnew));
                float p1 = f2t(__expf(s[j][2 * rr + 1] - mnew));
                s[j][2 * rr] = p0; s[j][2 * rr + 1] = p1;
                rs += p0 + p1;
            }
            rs += __shfl_xor_sync(0xffffffffu, rs, 1);
            rs += __shfl_xor_sync(0xffffffffu, rs, 2);
            l[rr] = l[rr] * corr + rs;
            mo[rr] = mnew;
            #pragma unroll
            for (int n = 0; n < 16; n++) {
                o[n][2 * rr] *= corr; o[n][2 * rr + 1] *= corr;
            }
        }

        #pragma unroll
        for (int j = 0; j < 8; j++) {
            *(float2*)&Pw[gid * PP + j * 8 + 2 * tig] =
                make_float2(s[j][0], s[j][1]);
            *(float2*)&Pw[(gid + 8) * PP + j * 8 + 2 * tig] =
                make_float2(s[j][2], s[j][3]);
        }
        __syncwarp();

        #pragma unroll
        for (int kk = 0; kk < 8; kk++) {
            unsigned a[4];
            a[0] = __float_as_uint(Pw[gid * PP + kk * 8 + tig]);
            a[1] = __float_as_uint(Pw[(gid + 8) * PP + kk * 8 + tig]);
            a[2] = __float_as_uint(Pw[gid * PP + kk * 8 + tig + 4]);
            a[3] = __float_as_uint(Pw[(gid + 8) * PP + kk * 8 + tig + 4]);
            #pragma unroll
            for (int n = 0; n < 16; n++) {
                unsigned b2[2];
                b2[0] = __float_as_uint(Vs[(kk * 8 + tig) * VP + n * 8 + gid]);
                b2[1] = __float_as_uint(Vs[(kk * 8 + tig + 4) * VP + n * 8 + gid]);
                mma_tf32(o[n], a, b2);
            }
        }
    }

    /* epilogue: normalize; write bf16 hi/lo in slot order */
    int t0 = b * SEQ + qt * 128 + w * 16 + gid;
    int t1 = t0 + 8;
    size_t r0 = (size_t)g_slot[t0] * DMODEL + h * HD;
    size_t r1 = (size_t)g_slot[t1] * DMODEL + h * HD;
    unsigned* AH = (unsigned*)g_aoh;
    unsigned* AL = (unsigned*)g_aol;
    float inv0 = 1.f / l[0], inv1 = 1.f / l[1];
    #pragma unroll
    for (int n = 0; n < 16; n++) {
        float v0 = o[n][0] * inv0, v1 = o[n][1] * inv0;
        float v2 = o[n][2] * inv1, v3 = o[n][3] * inv1;
        size_t i0 = (r0 + n * 8 + 2 * tig) >> 1;
        size_t i1 = (r1 + n * 8 + 2 * tig) >> 1;
        AH[i0] = pk2bf(v0, v1);
        AL[i0] = pk2bf(bfres(v0), bfres(v1));
        AH[i1] = pk2bf(v2, v3);
        AL[i1] = pk2bf(bfres(v2), bfres(v3));
    }
}

/* ---------------- output projection: bf16x3 ----------------
 * A (attn out) and B (Wo) pre-split into bf16 hi/lo. Per k16 stage:
 * acc += Ah*Bh + Ah*Bl + Al*Bh.  m16n8k16 bf16 mma, fp32 accumulate. */
#define OAP 12       /* A smem pitch, uints (8 used) */
#define OBP 132      /* B smem pitch, uints (128 used) */
#define OASZ (128*OAP)
#define OBSZ (8*OBP)

__global__ void __launch_bounds__(256, 2) proj_o_kernel(float* __restrict__ out)
{
    __shared__ unsigned sAh[2 * OASZ];
    __shared__ unsigned sAl[2 * OASZ];
    __shared__ unsigned sBh[2 * OBSZ];
    __shared__ unsigned sBl[2 * OBSZ];

    const int m = blockIdx.z;
    const int cnt = g_cnt[m];
    const int row0 = blockIdx.y * BM, col0 = blockIdx.x * BN;
    if (row0 >= cnt) return;

    const __nv_bfloat16* Xh = g_aoh + (size_t)m * R_TOK * DMODEL;
    const __nv_bfloat16* Xl = g_aol + (size_t)m * R_TOK * DMODEL;
    const unsigned* Wh = g_woh + (size_t)m * (DMODEL / 2) * DMODEL;
    const unsigned* Wl = g_wol + (size_t)m * (DMODEL / 2) * DMODEL;

    const int tid = threadIdx.x;
    const int lane = tid & 31, w = tid >> 5;
    const int wm = (w >> 2) * 64, wn = (w & 3) * 32;
    const int gid = lane >> 2, tig = lane & 3;

    const unsigned bAh = (unsigned)__cvta_generic_to_shared(sAh);
    const unsigned bAl = (unsigned)__cvta_generic_to_shared(sAl);
    const unsigned bBh = (unsigned)__cvta_generic_to_shared(sBh);
    const unsigned bBl = (unsigned)__cvta_generic_to_shared(sBl);

    /* per-thread copy slots: A: row=tid>>1, half=tid&1 ; B: kp=tid>>5, nq=tid&31 */
    const int arow = tid >> 1, ahalf = tid & 1;
    const int bkp = tid >> 5, bnq = tid & 31;

    auto issue = [&](int buf, int k0) {
        size_t aoff = (size_t)(row0 + arow) * DMODEL + k0 + ahalf * 8;
        unsigned adst = (unsigned)(buf * OASZ + arow * OAP + ahalf * 4) * 4;
        CP16(bAh + adst, Xh + aoff);
        CP16(bAl + adst, Xl + aoff);
        size_t boff = (size_t)((k0 >> 1) + bkp) * DMODEL + col0 + bnq * 4;
        unsigned bdst = (unsigned)(buf * OBSZ + bkp * OBP + bnq * 4) * 4;
        CP16(bBh + bdst, Wh + boff);
        CP16(bBl + bdst, Wl + boff);
        CP_COMMIT();
    };

    float acc[4][4][4] = {};
    issue(0, 0);
    const int T = DMODEL / 16;
    for (int t = 0; t < T; t++) {
        const int buf = t & 1;
        if (t + 1 < T) { issue(buf ^ 1, (t + 1) * 16); CP_WAIT(1); }
        else           { CP_WAIT(0); }
        __syncthreads();
        const unsigned* Ah = sAh + buf * OASZ;
        const unsigned* Al = sAl + buf * OASZ;
        const unsigned* Bh = sBh + buf * OBSZ;
        const unsigned* Bl = sBl + buf * OBSZ;

        unsigned ah[4][4], bh[4][2];
        #pragma unroll
        for (int i = 0; i < 4; i++) {
            int rb = (wm + i * 16 + gid) * OAP;
            ah[i][0] = Ah[rb + tig];
            ah[i][1] = Ah[rb + 8 * OAP + tig];
            ah[i][2] = Ah[rb + tig + 4];
            ah[i][3] = Ah[rb + 8 * OAP + tig + 4];
        }
        #pragma unroll
        for (int j = 0; j < 4; j++) {
            int cb = wn + j * 8 + gid;
            bh[j][0] = Bh[tig * OBP + cb];
            bh[j][1] = Bh[(tig + 4) * OBP + cb];
        }
        #pragma unroll
        for (int i = 0; i < 4; i++)
            #pragma unroll
            for (int j = 0; j < 4; j++)
                mma_bf16(acc[i][j], ah[i], bh[j]);

        unsigned bl[4][2];
        #pragma unroll
        for (int j = 0; j < 4; j++) {
            int cb = wn + j * 8 + gid;
            bl[j][0] = Bl[tig * OBP + cb];
            bl[j][1] = Bl[(tig + 4) * OBP + cb];
        }
        #pragma unroll
        for (int i = 0; i < 4; i++)
            #pragma unroll
            for (int j = 0; j < 4; j++)
                mma_bf16(acc[i][j], ah[i], bl[j]);

        unsigned al[4][4];
        #pragma unroll
        for (int i = 0; i < 4; i++) {
            int rb = (wm + i * 16 + gid) * OAP;
            al[i][0] = Al[rb + tig];
            al[i][1] = Al[rb + 8 * OAP + tig];
            al[i][2] = Al[rb + tig + 4];
            al[i][3] = Al[rb + 8 * OAP + tig + 4];
        }
        #pragma unroll
        for (int i = 0; i < 4; i++)
            #pragma unroll
            for (int j = 0; j < 4; j++)
                mma_bf16(acc[i][j], al[i], bh[j]);

        __syncthreads();
    }

    #pragma unroll
    for (int i = 0; i < 4; i++) {
        #pragma unroll
        for (int half = 0; half < 2; half++) {
            int r = row0 + wm + i * 16 + gid + half * 8;
            if (r >= cnt) continue;
            int tok = g_tok[m * R_TOK + r];
            #pragma unroll
            for (int j = 0; j < 4; j++) {
                int c = col0 + wn + j * 8 + tig * 2;
                out[(size_t)tok * DMODEL + c]     = acc[i][j][half * 2 + 0];
                out[(size_t)tok * DMODEL + c + 1] = acc[i][j][half * 2 + 1];
            }
        }
    }
}

/* ---------------- launch ---------------- */
extern "C" void kernel_launch(void* const* d_in, const int* in_sizes, int n_in,
                              void* d_out, int out_size) {
    (void)in_sizes; (void)n_in; (void)out_size;
    const float* x  = (const float*)d_in[0];
    const float* fc = (const float*)d_in[1];
    const float* Wq = (const float*)d_in[2];
    const float* Wk = (const float*)d_in[3];
    const float* Wv = (const float*)d_in[4];
    const float* Wo = (const float*)d_in[5];
    const int*   mid = (const int*)d_in[6];
    float* out = (float*)d_out;

    static int attr_done = 0;
    if (!attr_done) {
        cudaFuncSetAttribute(attn_kernel,
            cudaFuncAttributeMaxDynamicSharedMemorySize, ATTN_SMEM);
        attr_done = 1;
    }

    zero_cnt_kernel<<<1, 32>>>();
    assign_kernel<<<R_TOK / 256, 256>>>(mid);
    gather_x_kernel<<<R_TOK, 256>>>(x);
    pad_kernel<<<dim3(BM, NMOD), 256>>>();
    prep_kernel<<<4096, 256>>>(Wq, Wo);
    wsum_kernel<<<2048, 256>>>(Wk, Wv);
    proj_q_kernel<<<dim3(DMODEL / BN, R_TOK / BM, NMOD), 256>>>(fc);
    proj_kv_kernel<<<dim3((2 * KVE) / BN, R_TOK / BM, NMOD), 256>>>(fc);
    attn_kernel<<<dim3(SEQ / 128, NH, BDIM), 256, ATTN_SMEM>>>();
    proj_o_kernel<<<dim3(DMODEL / BN, R_TOK / BM, NMOD), 256>>>(out);
}

// round 8
// speedup vs baseline: 1.2446x; 1.0097x over previous
#include <cuda_runtime.h>
#include <cuda_bf16.h>
#include <math.h>

#define BDIM 2
#define SEQ 2048
#define DMODEL 2048
#define NH 16
#define NKV 4
#define HD 128
#define NMOD 2
#define R_TOK (BDIM*SEQ)
#define KVE (NKV*HD)

#define BM 128
#define BN 128
/* packed tile block: one (row-tile 128) x (kb of 8 k) = 1024 floats (A),
 * one (n-tile 128) x (kb of 8 k) = 1024 floats (B).
 * row-tile stride in A = DMODEL/8 * 1024 = 262144 floats; same for B n-tile. */
#define TILE_BLK 262144

/* ---------------- scratch ---------------- */
__device__ int   g_cnt[NMOD];
__device__ int   g_tok[NMOD*R_TOK];
__device__ int   g_slot[R_TOK];
__device__ float g_wk[NMOD*DMODEL*KVE];             /* packed */
__device__ float g_wv[NMOD*DMODEL*KVE];             /* packed */
__device__ float g_xt[(size_t)NMOD*R_TOK*DMODEL];   /* packed, slot order */
__device__ float g_wqt[(size_t)NMOD*DMODEL*DMODEL]; /* packed */
__device__ unsigned g_woh[(size_t)NMOD*(DMODEL/2)*DMODEL];
__device__ unsigned g_wol[(size_t)NMOD*(DMODEL/2)*DMODEL];
__device__ float g_q[(size_t)BDIM*NH*SEQ*HD];
__device__ float g_k[(size_t)BDIM*NKV*SEQ*HD];
__device__ float g_v[(size_t)BDIM*NKV*SEQ*HD];
__device__ __nv_bfloat16 g_aoh[(size_t)NMOD*R_TOK*DMODEL];
__device__ __nv_bfloat16 g_aol[(size_t)NMOD*R_TOK*DMODEL];

/* ---------------- helpers ---------------- */
__device__ __forceinline__ float f2t(float f) {
    unsigned u;
    asm("cvt.rna.tf32.f32 %0, %1;" : "=r"(u) : "f"(f));
    return __uint_as_float(u);
}
__device__ __forceinline__ unsigned f2tu(float f) {
    unsigned u;
    asm("cvt.rna.tf32.f32 %0, %1;" : "=r"(u) : "f"(f));
    return u;
}
__device__ __forceinline__ void mma_tf32(float* d, const unsigned* a, const unsigned* b) {
    asm volatile(
        "mma.sync.aligned.m16n8k8.row.col.f32.tf32.tf32.f32 "
        "{%0,%1,%2,%3},{%4,%5,%6,%7},{%8,%9},{%0,%1,%2,%3};"
        : "+f"(d[0]), "+f"(d[1]), "+f"(d[2]), "+f"(d[3])
        : "r"(a[0]), "r"(a[1]), "r"(a[2]), "r"(a[3]), "r"(b[0]), "r"(b[1]));
}
__device__ __forceinline__ void mma_bf16(float* d, const unsigned* a, const unsigned* b) {
    asm volatile(
        "mma.sync.aligned.m16n8k16.row.col.f32.bf16.bf16.f32 "
        "{%0,%1,%2,%3},{%4,%5,%6,%7},{%8,%9},{%0,%1,%2,%3};"
        : "+f"(d[0]), "+f"(d[1]), "+f"(d[2]), "+f"(d[3])
        : "r"(a[0]), "r"(a[1]), "r"(a[2]), "r"(a[3]), "r"(b[0]), "r"(b[1]));
}
__device__ __forceinline__ unsigned pk2bf(float a, float b) {
    return (unsigned)__bfloat16_as_ushort(__float2bfloat16(a)) |
           ((unsigned)__bfloat16_as_ushort(__float2bfloat16(b)) << 16);
}
__device__ __forceinline__ float bfres(float v) {
    return v - __bfloat162float(__float2bfloat16(v));
}

/* A-fragment-packed index inside one row-tile (128 rows x 2048 k):
 * kb*1024 + (rr/16)*128 + (gid*4 + kk&3)*4 + (hi + 2*(kk>>2))
 * where rr=r%128, gid=(rr%16)&7, hi=(rr%16)>>3. */
__device__ __forceinline__ int apack_off(int rr, int k) {
    int kb = k >> 3, kk = k & 7;
    int g = rr >> 4, r16 = rr & 15;
    int gid = r16 & 7, hi = r16 >> 3;
    return kb * 1024 + g * 128 + (gid * 4 + (kk & 3)) * 4 + hi + ((kk >> 2) << 1);
}
/* B-fragment-packed index inside one n-tile (2048 k x 128 n):
 * kb*1024 + ((nn&127)/8)*64 + (gid*4 + kk&3)*2 + (kk>>2), gid=nn&7 */
__device__ __forceinline__ int bpack_off(int k, int nn) {
    int kb = k >> 3, kk = k & 7;
    int jb = nn >> 3, gid = nn & 7;
    return kb * 1024 + jb * 64 + (gid * 4 + (kk & 3)) * 2 + (kk >> 2);
}

#define CP16(dst, src) \
    asm volatile("cp.async.cg.shared.global [%0], [%1], 16;" :: "r"(dst), "l"(src))
#define CP_COMMIT() asm volatile("cp.async.commit_group;")
#define CP_WAIT(n)  asm volatile("cp.async.wait_group %0;" :: "n"(n))

/* ---------------- modality gather machinery ---------------- */
__global__ void zero_cnt_kernel() {
    if (threadIdx.x < NMOD) g_cnt[threadIdx.x] = 0;
}
__global__ void assign_kernel(const int* __restrict__ mid) {
    int t = blockIdx.x * blockDim.x + threadIdx.x;
    if (t < R_TOK) {
        int m = mid[t];
        int s = atomicAdd(&g_cnt[m], 1);
        g_tok[m * R_TOK + s] = t;
        g_slot[t] = m * R_TOK + s;
    }
}
/* gather x rows into packed A layout (tf32-rounded); thread = one kb chunk */
__global__ void gather_x_kernel(const float* __restrict__ x) {
    int t = blockIdx.x;
    int dst = g_slot[t];
    int m = dst / R_TOK, r = dst - m * R_TOK;
    float* base = g_xt + (size_t)m * R_TOK * DMODEL + (size_t)(r >> 7) * TILE_BLK;
    int rr = r & 127;
    const float* src = x + (size_t)t * DMODEL;
    for (int kb = threadIdx.x; kb < DMODEL / 8; kb += blockDim.x) {
        #pragma unroll
        for (int kk = 0; kk < 8; kk++)
            base[apack_off(rr, kb * 8 + kk)] = f2t(src[kb * 8 + kk]);
    }
}
__global__ void pad_kernel() {
    int m = blockIdx.y;
    int cnt = g_cnt[m];
    int ru = (cnt + BM - 1) & ~(BM - 1);
    int r = cnt + blockIdx.x;
    if (r >= ru) return;
    float* base = g_xt + (size_t)m * R_TOK * DMODEL + (size_t)(r >> 7) * TILE_BLK;
    int rr = r & 127;
    for (int kb = threadIdx.x; kb < DMODEL / 8; kb += blockDim.x) {
        #pragma unroll
        for (int kk = 0; kk < 8; kk++)
            base[apack_off(rr, kb * 8 + kk)] = 0.f;
    }
    size_t rowe = ((size_t)m * R_TOK + r) * DMODEL;
    uint4* hh = (uint4*)(g_aoh + rowe);
    uint4* ll = (uint4*)(g_aol + rowe);
    uint4 uz = make_uint4(0, 0, 0, 0);
    for (int i = threadIdx.x; i < DMODEL / 8; i += blockDim.x) { hh[i] = uz; ll[i] = uz; }
}

/* ---------------- prepass: pack Wq (tf32, B-frag layout) + Wo (bf16 pairs) */
__global__ void prep_kernel(const float* __restrict__ Wq,
                            const float* __restrict__ Wo) {
    /* Wq pack: unit = (m, k, jb8) -> 8 n values */
    const int NU = NMOD * DMODEL * (DMODEL / 8);
    for (int u = blockIdx.x * blockDim.x + threadIdx.x; u < NU;
         u += gridDim.x * blockDim.x) {
        int jb8 = u & (DMODEL / 8 - 1);
        int rest = u >> 8;
        int k = rest & (DMODEL - 1);
        int m = rest >> 11;
        int n0 = jb8 * 8;
        const float* src = Wq + ((size_t)(m * DMODEL + k)) * DMODEL + n0;
        float* dst = g_wqt + (size_t)m * (DMODEL / 128) * TILE_BLK
                   + (size_t)(n0 >> 7) * TILE_BLK;
        #pragma unroll
        for (int q = 0; q < 8; q++)
            dst[bpack_off(k, (n0 & 127) + q)] = f2t(src[q]);
    }
    /* Wo: bf16 hi/lo k-pair interleave (unchanged) */
    const int NP = NMOD * (DMODEL / 2) * DMODEL;
    for (int j = blockIdx.x * blockDim.x + threadIdx.x; j < NP;
         j += gridDim.x * blockDim.x) {
        int n = j & (DMODEL - 1);
        int rest = j >> 11;
        int k2 = rest & (DMODEL / 2 - 1);
        int m = rest >> 10;
        size_t base = ((size_t)(m * DMODEL + 2 * k2)) * DMODEL + n;
        float w0 = Wo[base], w1 = Wo[base + DMODEL];
        g_woh[j] = pk2bf(w0, w1);
        g_wol[j] = pk2bf(bfres(w0), bfres(w1));
    }
}
/* Wk/Wv modality-sum into packed B layout */
__global__ void wsum_kernel(const float* __restrict__ Wk,
                            const float* __restrict__ Wv) {
    const int NU = NMOD * DMODEL * (KVE / 8);   /* 262144 units each */
    for (int u = blockIdx.x * blockDim.x + threadIdx.x; u < 2 * NU;
         u += gridDim.x * blockDim.x) {
        int isV = u >= NU;
        int v = isV ? u - NU : u;
        int jb8 = v & (KVE / 8 - 1);
        int rest = v >> 6;
        int k = rest & (DMODEL - 1);
        int m = rest >> 11;
        int n0 = jb8 * 8;
        const float* W = isV ? Wv : Wk;
        size_t sbase = ((size_t)m * 2 * DMODEL + k) * KVE + n0;
        float* dst = (isV ? g_wv : g_wk) + (size_t)m * (KVE / 128) * TILE_BLK
                   + (size_t)(n0 >> 7) * TILE_BLK;
        #pragma unroll
        for (int q = 0; q < 8; q++)
            dst[bpack_off(k, (n0 & 127) + q)] =
                f2t(W[sbase + q] + W[sbase + (size_t)DMODEL * KVE + q]);
    }
}

/* ---------------- packed tf32 GEMM core (128x128, 2 CTA/SM) ----------------
 * Xp: packed A row-tile base; Wp: packed B n-tile base. K = 2048.
 * Per k8: 4x LDS.128 (A frags) + 4x LDS.64 (B frags) + 16 mma. */
__device__ __forceinline__ void gemm_tf32p(
    const float* __restrict__ Xp, const float* __restrict__ Wp,
    float (&acc)[4][4][4], float* smem)
{
    const int tid = threadIdx.x;
    const int lane = tid & 31, w = tid >> 5;
    const int wg = (w >> 2) * 4;      /* A group base (row/16) */
    const int jb0 = (w & 3) * 4;      /* B jb base (col/8)   */
    float* As = smem;                 /* 2 stages x 2048 floats */
    float* Bs = smem + 4096;
    const unsigned sA = (unsigned)__cvta_generic_to_shared(As);
    const unsigned sB = (unsigned)__cvta_generic_to_shared(Bs);

    auto issue = [&](int buf, int k0) {
        const float* aS = Xp + (k0 >> 3) * 1024;
        const float* bS = Wp + (k0 >> 3) * 1024;
        unsigned aD = sA + buf * 8192, bD = sB + buf * 8192;
        CP16(aD + tid * 16, aS + tid * 4);
        CP16(aD + (tid + 256) * 16, aS + (tid + 256) * 4);
        CP16(bD + tid * 16, bS + tid * 4);
        CP16(bD + (tid + 256) * 16, bS + (tid + 256) * 4);
        CP_COMMIT();
    };

    issue(0, 0);
    const int T = DMODEL / 16;
    for (int t = 0; t < T; t++) {
        const int buf = t & 1;
        if (t + 1 < T) { issue(buf ^ 1, (t + 1) * 16); CP_WAIT(1); }
        else           { CP_WAIT(0); }
        __syncthreads();
        #pragma unroll
        for (int kb = 0; kb < 2; kb++) {
            const float* Ab = As + buf * 2048 + kb * 1024;
            const float* Bb = Bs + buf * 2048 + kb * 1024;
            unsigned a[4][4], b[4][2];
            #pragma unroll
            for (int i = 0; i < 4; i++) {
                float4 v = *(const float4*)&Ab[(wg + i) * 128 + lane * 4];
                a[i][0] = __float_as_uint(v.x);
                a[i][1] = __float_as_uint(v.y);
                a[i][2] = __float_as_uint(v.z);
                a[i][3] = __float_as_uint(v.w);
            }
            #pragma unroll
            for (int j = 0; j < 4; j++) {
                float2 u = *(const float2*)&Bb[(jb0 + j) * 64 + lane * 2];
                b[j][0] = __float_as_uint(u.x);
                b[j][1] = __float_as_uint(u.y);
            }
            #pragma unroll
            for (int i = 0; i < 4; i++)
                #pragma unroll
                for (int j = 0; j < 4; j++)
                    mma_tf32(acc[i][j], a[i], b[j]);
        }
        __syncthreads();
    }
}

/* ---------------- Q projection + RoPE ---------------- */
__global__ void __launch_bounds__(256, 2) proj_q_kernel(
    const float* __restrict__ fc)
{
    __shared__ __align__(16) float smem[8192];
    const int m = blockIdx.z;
    const int cnt = g_cnt[m];
    const int row0 = blockIdx.y * BM, col0 = blockIdx.x * BN;
    if (row0 >= cnt) return;
    float acc[4][4][4] = {};
    gemm_tf32p(g_xt + (size_t)m * R_TOK * DMODEL + (size_t)(row0 >> 7) * TILE_BLK,
               g_wqt + (size_t)m * (DMODEL / 128) * TILE_BLK
                     + (size_t)(col0 >> 7) * TILE_BLK,
               acc, smem);

    const int lane = threadIdx.x & 31, w = threadIdx.x >> 5;
    const int wm = (w >> 2) * 64, wn = (w & 3) * 32;
    const int gid = lane >> 2, tig = lane & 3;
    #pragma unroll
    for (int i = 0; i < 4; i++) {
        #pragma unroll
        for (int half = 0; half < 2; half++) {
            int r = row0 + wm + i * 16 + gid + half * 8;
            if (r >= cnt) continue;
            int tok = g_tok[m * R_TOK + r];
            int b_ = tok >> 11, s = tok & (SEQ - 1);
            #pragma unroll
            for (int j = 0; j < 4; j++) {
                int c = col0 + wn + j * 8 + tig * 2;
                float e = acc[i][j][half * 2 + 0];
                float o = acc[i][j][half * 2 + 1];
                int h = c >> 7, d = c & 127, pr = d >> 1;
                float cv = fc[(size_t)s * 256 + pr * 4 + 0];
                float sv = fc[(size_t)s * 256 + pr * 4 + 2];
                size_t base = (((size_t)b_ * NH + h) * SEQ + s) * HD + d;
                g_q[base]     = e * cv + o * sv;
                g_q[base + 1] = o * cv - e * sv;
            }
        }
    }
}

/* ---------------- K/V projection (+RoPE on K) ---------------- */
__global__ void __launch_bounds__(256, 2) proj_kv_kernel(
    const float* __restrict__ fc)
{
    __shared__ __align__(16) float smem[8192];
    const int m = blockIdx.z;
    const int cnt = g_cnt[m];
    const int row0 = blockIdx.y * BM;
    if (row0 >= cnt) return;
    const int n0 = blockIdx.x * BN;           /* 0..384 K ; 512..896 V */
    const bool isV = (n0 >= KVE);
    const int c0base = isV ? n0 - KVE : n0;
    const float* Wp = (isV ? g_wv : g_wk)
                    + (size_t)m * (KVE / 128) * TILE_BLK
                    + (size_t)(c0base >> 7) * TILE_BLK;

    float acc[4][4][4] = {};
    gemm_tf32p(g_xt + (size_t)m * R_TOK * DMODEL + (size_t)(row0 >> 7) * TILE_BLK,
               Wp, acc, smem);

    const int lane = threadIdx.x & 31, w = threadIdx.x >> 5;
    const int wm = (w >> 2) * 64, wn = (w & 3) * 32;
    const int gid = lane >> 2, tig = lane & 3;
    #pragma unroll
    for (int i = 0; i < 4; i++) {
        #pragma unroll
        for (int half = 0; half < 2; half++) {
            int r = row0 + wm + i * 16 + gid + half * 8;
            if (r >= cnt) continue;
            int tok = g_tok[m * R_TOK + r];
            int b_ = tok >> 11, s = tok & (SEQ - 1);
            #pragma unroll
            for (int j = 0; j < 4; j++) {
                int c = c0base + wn + j * 8 + tig * 2;
                int kvh = c >> 7, d = c & 127;
                float e = acc[i][j][half * 2 + 0];
                float o = acc[i][j][half * 2 + 1];
                size_t base = (((size_t)b_ * NKV + kvh) * SEQ + s) * HD + d;
                if (!isV) {
                    int pr = d >> 1;
                    float cv = fc[(size_t)s * 256 + pr * 4 + 0];
                    float sv = fc[(size_t)s * 256 + pr * 4 + 2];
                    g_k[base]     = e * cv + o * sv;
                    g_k[base + 1] = o * cv - e * sv;
                } else {
                    g_v[base]     = e;
                    g_v[base + 1] = o;
                }
            }
        }
    }
}

/* ---------------- flash attention: 128 q-rows/CTA, 8 warps (round-7) ------ */
#define KP 132
#define VP 136
#define PP 68
#define ATTN_SMEM ((64*KP + 64*VP + 128*PP) * 4)

__global__ void __launch_bounds__(256) attn_kernel() {
    extern __shared__ float sm[];
    float* Ks = sm;
    float* Vs = Ks + 64 * KP;
    float* Ps = Vs + 64 * VP;

    const int qt = blockIdx.x, h = blockIdx.y, b = blockIdx.z;
    const int kvh = h >> 2;
    const int tid = threadIdx.x;
    const int w = tid >> 5, lane = tid & 31, gid = lane >> 2, tig = lane & 3;
    const float scale = 0.08838834764831845f;

    const float* Qg = g_q + (((size_t)b * NH + h) * SEQ + qt * 128 + w * 16) * HD;
    unsigned QA[16][4];
    #pragma unroll
    for (int ks = 0; ks < 16; ks++) {
        QA[ks][0] = f2tu(Qg[gid * HD + 8 * ks + tig] * scale);
        QA[ks][1] = f2tu(Qg[(gid + 8) * HD + 8 * ks + tig] * scale);
        QA[ks][2] = f2tu(Qg[gid * HD + 8 * ks + tig + 4] * scale);
        QA[ks][3] = f2tu(Qg[(gid + 8) * HD + 8 * ks + tig + 4] * scale);
    }

    float o[16][4];
    #pragma unroll
    for (int n = 0; n < 16; n++)
        #pragma unroll
        for (int q = 0; q < 4; q++) o[n][q] = 0.f;
    float mo[2] = {-1e30f, -1e30f}, l[2] = {0.f, 0.f};

    const float* Kg = g_k + ((size_t)b * NKV + kvh) * SEQ * HD;
    const float* Vg = g_v + ((size_t)b * NKV + kvh) * SEQ * HD;
    float* Pw = Ps + w * 16 * PP;

    for (int kt = 0; kt < SEQ / 64; kt++) {
        __syncthreads();
        const float* Kt = Kg + (size_t)kt * 64 * HD;
        const float* Vt = Vg + (size_t)kt * 64 * HD;
        #pragma unroll
        for (int it = 0; it < 8; it++) {
            int i = tid + it * 256;
            int r = i >> 5, c4 = (i & 31) << 2;
            float4 kv4 = *(const float4*)&Kt[r * HD + c4];
            float4 vv4 = *(const float4*)&Vt[r * HD + c4];
            kv4.x = f2t(kv4.x); kv4.y = f2t(kv4.y);
            kv4.z = f2t(kv4.z); kv4.w = f2t(kv4.w);
            vv4.x = f2t(vv4.x); vv4.y = f2t(vv4.y);
            vv4.z = f2t(vv4.z); vv4.w = f2t(vv4.w);
            *(float4*)&Ks[r * KP + c4] = kv4;
            *(float4*)&Vs[r * VP + c4] = vv4;
        }
        __syncthreads();

        float s[8][4] = {};
        #pragma unroll
        for (int ks = 0; ks < 16; ks++) {
            #pragma unroll
            for (int j = 0; j < 8; j++) {
                unsigned b2[2];
                b2[0] = __float_as_uint(Ks[(j * 8 + gid) * KP + ks * 8 + tig]);
                b2[1] = __float_as_uint(Ks[(j * 8 + gid) * KP + ks * 8 + tig + 4]);
                mma_tf32(s[j], QA[ks], b2);
            }
        }

        #pragma unroll
        for (int rr = 0; rr < 2; rr++) {
            float mx = -1e30f;
            #pragma unroll
            for (int j = 0; j < 8; j++)
                mx = fmaxf(mx, fmaxf(s[j][2 * rr], s[j][2 * rr + 1]));
            mx = fmaxf(mx, __shfl_xor_sync(0xffffffffu, mx, 1));
            mx = fmaxf(mx, __shfl_xor_sync(0xffffffffu, mx, 2));
            float mnew = fmaxf(mo[rr], mx);
            float corr = __expf(mo[rr] - mnew);
            float rs = 0.f;
            #pragma unroll
            for (int j = 0; j < 8; j++) {
                float p0 = f2t(__expf(s[j][2 * rr] - mnew));
                float p1 = f2t(__expf(s[j][2 * rr + 1] - mnew));
                s[j][2 * rr] = p0; s[j][2 * rr + 1] = p1;
                rs += p0 + p1;
            }
            rs += __shfl_xor_sync(0xffffffffu, rs, 1);
            rs += __shfl_xor_sync(0xffffffffu, rs, 2);
            l[rr] = l[rr] * corr + rs;
            mo[rr] = mnew;
            #pragma unroll
            for (int n = 0; n < 16; n++) {
                o[n][2 * rr] *= corr; o[n][2 * rr + 1] *= corr;
            }
        }

        #pragma unroll
        for (int j = 0; j < 8; j++) {
            *(float2*)&Pw[gid * PP + j * 8 + 2 * tig] =
                make_float2(s[j][0], s[j][1]);
            *(float2*)&Pw[(gid + 8) * PP + j * 8 + 2 * tig] =
                make_float2(s[j][2], s[j][3]);
        }
        __syncwarp();

        #pragma unroll
        for (int kk = 0; kk < 8; kk++) {
            unsigned a[4];
            a[0] = __float_as_uint(Pw[gid * PP + kk * 8 + tig]);
            a[1] = __float_as_uint(Pw[(gid + 8) * PP + kk * 8 + tig]);
            a[2] = __float_as_uint(Pw[gid * PP + kk * 8 + tig + 4]);
            a[3] = __float_as_uint(Pw[(gid + 8) * PP + kk * 8 + tig + 4]);
            #pragma unroll
            for (int n = 0; n < 16; n++) {
                unsigned b2[2];
                b2[0] = __float_as_uint(Vs[(kk * 8 + tig) * VP + n * 8 + gid]);
                b2[1] = __float_as_uint(Vs[(kk * 8 + tig + 4) * VP + n * 8 + gid]);
                mma_tf32(o[n], a, b2);
            }
        }
    }

    int t0 = b * SEQ + qt * 128 + w * 16 + gid;
    int t1 = t0 + 8;
    size_t r0 = (size_t)g_slot[t0] * DMODEL + h * HD;
    size_t r1 = (size_t)g_slot[t1] * DMODEL + h * HD;
    unsigned* AH = (unsigned*)g_aoh;
    unsigned* AL = (unsigned*)g_aol;
    float inv0 = 1.f / l[0], inv1 = 1.f / l[1];
    #pragma unroll
    for (int n = 0; n < 16; n++) {
        float v0 = o[n][0] * inv0, v1 = o[n][1] * inv0;
        float v2 = o[n][2] * inv1, v3 = o[n][3] * inv1;
        size_t i0 = (r0 + n * 8 + 2 * tig) >> 1;
        size_t i1 = (r1 + n * 8 + 2 * tig) >> 1;
        AH[i0] = pk2bf(v0, v1);
        AL[i0] = pk2bf(bfres(v0), bfres(v1));
        AH[i1] = pk2bf(v2, v3);
        AL[i1] = pk2bf(bfres(v2), bfres(v3));
    }
}

/* ---------------- output projection: bf16x3 (round-7) ---------------- */
#define OAP 12
#define OBP 132
#define OASZ (128*OAP)
#define OBSZ (8*OBP)

__global__ void __launch_bounds__(256, 2) proj_o_kernel(float* __restrict__ out)
{
    __shared__ unsigned sAh[2 * OASZ];
    __shared__ unsigned sAl[2 * OASZ];
    __shared__ unsigned sBh[2 * OBSZ];
    __shared__ unsigned sBl[2 * OBSZ];

    const int m = blockIdx.z;
    const int cnt = g_cnt[m];
    const int row0 = blockIdx.y * BM, col0 = blockIdx.x * BN;
    if (row0 >= cnt) return;

    const __nv_bfloat16* Xh = g_aoh + (size_t)m * R_TOK * DMODEL;
    const __nv_bfloat16* Xl = g_aol + (size_t)m * R_TOK * DMODEL;
    const unsigned* Wh = g_woh + (size_t)m * (DMODEL / 2) * DMODEL;
    const unsigned* Wl = g_wol + (size_t)m * (DMODEL / 2) * DMODEL;

    const int tid = threadIdx.x;
    const int lane = tid & 31, w = tid >> 5;
    const int wm = (w >> 2) * 64, wn = (w & 3) * 32;
    const int gid = lane >> 2, tig = lane & 3;

    const unsigned bAh = (unsigned)__cvta_generic_to_shared(sAh);
    const unsigned bAl = (unsigned)__cvta_generic_to_shared(sAl);
    const unsigned bBh = (unsigned)__cvta_generic_to_shared(sBh);
    const unsigned bBl = (unsigned)__cvta_generic_to_shared(sBl);

    const int arow = tid >> 1, ahalf = tid & 1;
    const int bkp = tid >> 5, bnq = tid & 31;

    auto issue = [&](int buf, int k0) {
        size_t aoff = (size_t)(row0 + arow) * DMODEL + k0 + ahalf * 8;
        unsigned adst = (unsigned)(buf * OASZ + arow * OAP + ahalf * 4) * 4;
        CP16(bAh + adst, Xh + aoff);
        CP16(bAl + adst, Xl + aoff);
        size_t boff = (size_t)((k0 >> 1) + bkp) * DMODEL + col0 + bnq * 4;
        unsigned bdst = (unsigned)(buf * OBSZ + bkp * OBP + bnq * 4) * 4;
        CP16(bBh + bdst, Wh + boff);
        CP16(bBl + bdst, Wl + boff);
        CP_COMMIT();
    };

    float acc[4][4][4] = {};
    issue(0, 0);
    const int T = DMODEL / 16;
    for (int t = 0; t < T; t++) {
        const int buf = t & 1;
        if (t + 1 < T) { issue(buf ^ 1, (t + 1) * 16); CP_WAIT(1); }
        else           { CP_WAIT(0); }
        __syncthreads();
        const unsigned* Ah = sAh + buf * OASZ;
        const unsigned* Al = sAl + buf * OASZ;
        const unsigned* Bh = sBh + buf * OBSZ;
        const unsigned* Bl = sBl + buf * OBSZ;

        unsigned ah[4][4], bh[4][2];
        #pragma unroll
        for (int i = 0; i < 4; i++) {
            int rb = (wm + i * 16 + gid) * OAP;
            ah[i][0] = Ah[rb + tig];
            ah[i][1] = Ah[rb + 8 * OAP + tig];
            ah[i][2] = Ah[rb + tig + 4];
            ah[i][3] = Ah[rb + 8 * OAP + tig + 4];
        }
        #pragma unroll
        for (int j = 0; j < 4; j++) {
            int cb = wn + j * 8 + gid;
            bh[j][0] = Bh[tig * OBP + cb];
            bh[j][1] = Bh[(tig + 4) * OBP + cb];
        }
        #pragma unroll
        for (int i = 0; i < 4; i++)
            #pragma unroll
            for (int j = 0; j < 4; j++)
                mma_bf16(acc[i][j], ah[i], bh[j]);

        unsigned bl[4][2];
        #pragma unroll
        for (int j = 0; j < 4; j++) {
            int cb = wn + j * 8 + gid;
            bl[j][0] = Bl[tig * OBP + cb];
            bl[j][1] = Bl[(tig + 4) * OBP + cb];
        }
        #pragma unroll
        for (int i = 0; i < 4; i++)
            #pragma unroll
            for (int j = 0; j < 4; j++)
                mma_bf16(acc[i][j], ah[i], bl[j]);

        unsigned al[4][4];
        #pragma unroll
        for (int i = 0; i < 4; i++) {
            int rb = (wm + i * 16 + gid) * OAP;
            al[i][0] = Al[rb + tig];
            al[i][1] = Al[rb + 8 * OAP + tig];
            al[i][2] = Al[rb + tig + 4];
            al[i][3] = Al[rb + 8 * OAP + tig + 4];
        }
        #pragma unroll
        for (int i = 0; i < 4; i++)
            #pragma unroll
            for (int j = 0; j < 4; j++)
                mma_bf16(acc[i][j], al[i], bh[j]);

        __syncthreads();
    }

    #pragma unroll
    for (int i = 0; i < 4; i++) {
        #pragma unroll
        for (int half = 0; half < 2; half++) {
            int r = row0 + wm + i * 16 + gid + half * 8;
            if (r >= cnt) continue;
            int tok = g_tok[m * R_TOK + r];
            #pragma unroll
            for (int j = 0; j < 4; j++) {
                int c = col0 + wn + j * 8 + tig * 2;
                out[(size_t)tok * DMODEL + c]     = acc[i][j][half * 2 + 0];
                out[(size_t)tok * DMODEL + c + 1] = acc[i][j][half * 2 + 1];
            }
        }
    }
}

/* ---------------- launch ---------------- */
extern "C" void kernel_launch(void* const* d_in, const int* in_sizes, int n_in,
                              void* d_out, int out_size) {
    (void)in_sizes; (void)n_in; (void)out_size;
    const float* x  = (const float*)d_in[0];
    const float* fc = (const float*)d_in[1];
    const float* Wq = (const float*)d_in[2];
    const float* Wk = (const float*)d_in[3];
    const float* Wv = (const float*)d_in[4];
    const float* Wo = (const float*)d_in[5];
    const int*   mid = (const int*)d_in[6];
    float* out = (float*)d_out;

    static int attr_done = 0;
    if (!attr_done) {
        cudaFuncSetAttribute(attn_kernel,
            cudaFuncAttributeMaxDynamicSharedMemorySize, ATTN_SMEM);
        attr_done = 1;
    }

    zero_cnt_kernel<<<1, 32>>>();
    assign_kernel<<<R_TOK / 256, 256>>>(mid);
    gather_x_kernel<<<R_TOK, 256>>>(x);
    pad_kernel<<<dim3(BM, NMOD), 256>>>();
    prep_kernel<<<4096, 256>>>(Wq, Wo);
    wsum_kernel<<<2048, 256>>>(Wk, Wv);
    proj_q_kernel<<<dim3(DMODEL / BN, R_TOK / BM, NMOD), 256>>>(fc);
    proj_kv_kernel<<<dim3((2 * KVE) / BN, R_TOK / BM, NMOD), 256>>>(fc);
    attn_kernel<<<dim3(SEQ / 128, NH, BDIM), 256, ATTN_SMEM>>>();
    proj_o_kernel<<<dim3(DMODEL / BN, R_TOK / BM, NMOD), 256>>>(out);
}

// round 9
// speedup vs baseline: 1.2750x; 1.0245x over previous
#include <cuda_runtime.h>
#include <cuda_bf16.h>
#include <math.h>

#define BDIM 2
#define SEQ 2048
#define DMODEL 2048
#define NH 16
#define NKV 4
#define HD 128
#define NMOD 2
#define R_TOK (BDIM*SEQ)
#define KVE (NKV*HD)

#define BM 128
#define BN 128
#define TILE_BLK 262144
#define GEMM_SMEM2 65536   /* 2 stages x (4096 A + 4096 B) floats */

/* ---------------- scratch ---------------- */
__device__ int   g_cnt[NMOD];
__device__ int   g_tok[NMOD*R_TOK];
__device__ int   g_slot[R_TOK];
__device__ float g_wk[NMOD*DMODEL*KVE];
__device__ float g_wv[NMOD*DMODEL*KVE];
__device__ float g_xt[(size_t)NMOD*R_TOK*DMODEL];
__device__ float g_wqt[(size_t)NMOD*DMODEL*DMODEL];
__device__ unsigned g_woh[(size_t)NMOD*(DMODEL/2)*DMODEL];
__device__ unsigned g_wol[(size_t)NMOD*(DMODEL/2)*DMODEL];
__device__ float g_q[(size_t)BDIM*NH*SEQ*HD];
__device__ float g_k[(size_t)BDIM*NKV*SEQ*HD];
__device__ float g_v[(size_t)BDIM*NKV*SEQ*HD];
__device__ __nv_bfloat16 g_aoh[(size_t)NMOD*R_TOK*DMODEL];
__device__ __nv_bfloat16 g_aol[(size_t)NMOD*R_TOK*DMODEL];

/* ---------------- helpers ---------------- */
__device__ __forceinline__ float f2t(float f) {
    unsigned u;
    asm("cvt.rna.tf32.f32 %0, %1;" : "=r"(u) : "f"(f));
    return __uint_as_float(u);
}
__device__ __forceinline__ unsigned f2tu(float f) {
    unsigned u;
    asm("cvt.rna.tf32.f32 %0, %1;" : "=r"(u) : "f"(f));
    return u;
}
__device__ __forceinline__ void mma_tf32(float* d, const unsigned* a, const unsigned* b) {
    asm volatile(
        "mma.sync.aligned.m16n8k8.row.col.f32.tf32.tf32.f32 "
        "{%0,%1,%2,%3},{%4,%5,%6,%7},{%8,%9},{%0,%1,%2,%3};"
        : "+f"(d[0]), "+f"(d[1]), "+f"(d[2]), "+f"(d[3])
        : "r"(a[0]), "r"(a[1]), "r"(a[2]), "r"(a[3]), "r"(b[0]), "r"(b[1]));
}
__device__ __forceinline__ void mma_bf16(float* d, const unsigned* a, const unsigned* b) {
    asm volatile(
        "mma.sync.aligned.m16n8k16.row.col.f32.bf16.bf16.f32 "
        "{%0,%1,%2,%3},{%4,%5,%6,%7},{%8,%9},{%0,%1,%2,%3};"
        : "+f"(d[0]), "+f"(d[1]), "+f"(d[2]), "+f"(d[3])
        : "r"(a[0]), "r"(a[1]), "r"(a[2]), "r"(a[3]), "r"(b[0]), "r"(b[1]));
}
__device__ __forceinline__ unsigned pk2bf(float a, float b) {
    return (unsigned)__bfloat16_as_ushort(__float2bfloat16(a)) |
           ((unsigned)__bfloat16_as_ushort(__float2bfloat16(b)) << 16);
}
__device__ __forceinline__ float bfres(float v) {
    return v - __bfloat162float(__float2bfloat16(v));
}

__device__ __forceinline__ int apack_off(int rr, int k) {
    int kb = k >> 3, kk = k & 7;
    int g = rr >> 4, r16 = rr & 15;
    int gid = r16 & 7, hi = r16 >> 3;
    return kb * 1024 + g * 128 + (gid * 4 + (kk & 3)) * 4 + hi + ((kk >> 2) << 1);
}
__device__ __forceinline__ int bpack_off(int k, int nn) {
    int kb = k >> 3, kk = k & 7;
    int jb = nn >> 3, gid = nn & 7;
    return kb * 1024 + jb * 64 + (gid * 4 + (kk & 3)) * 2 + (kk >> 2);
}

#define CP16(dst, src) \
    asm volatile("cp.async.cg.shared.global [%0], [%1], 16;" :: "r"(dst), "l"(src))
#define CP_COMMIT() asm volatile("cp.async.commit_group;")
#define CP_WAIT(n)  asm volatile("cp.async.wait_group %0;" :: "n"(n))

/* ---------------- modality gather machinery ---------------- */
__global__ void zero_cnt_kernel() {
    if (threadIdx.x < NMOD) g_cnt[threadIdx.x] = 0;
}
__global__ void assign_kernel(const int* __restrict__ mid) {
    int t = blockIdx.x * blockDim.x + threadIdx.x;
    if (t < R_TOK) {
        int m = mid[t];
        int s = atomicAdd(&g_cnt[m], 1);
        g_tok[m * R_TOK + s] = t;
        g_slot[t] = m * R_TOK + s;
    }
}
__global__ void gather_x_kernel(const float* __restrict__ x) {
    int t = blockIdx.x;
    int dst = g_slot[t];
    int m = dst / R_TOK, r = dst - m * R_TOK;
    float* base = g_xt + (size_t)m * R_TOK * DMODEL + (size_t)(r >> 7) * TILE_BLK;
    int rr = r & 127;
    const float* src = x + (size_t)t * DMODEL;
    for (int kb = threadIdx.x; kb < DMODEL / 8; kb += blockDim.x) {
        #pragma unroll
        for (int kk = 0; kk < 8; kk++)
            base[apack_off(rr, kb * 8 + kk)] = f2t(src[kb * 8 + kk]);
    }
}
__global__ void pad_kernel() {
    int m = blockIdx.y;
    int cnt = g_cnt[m];
    int ru = (cnt + BM - 1) & ~(BM - 1);
    int r = cnt + blockIdx.x;
    if (r >= ru) return;
    float* base = g_xt + (size_t)m * R_TOK * DMODEL + (size_t)(r >> 7) * TILE_BLK;
    int rr = r & 127;
    for (int kb = threadIdx.x; kb < DMODEL / 8; kb += blockDim.x) {
        #pragma unroll
        for (int kk = 0; kk < 8; kk++)
            base[apack_off(rr, kb * 8 + kk)] = 0.f;
    }
    size_t rowe = ((size_t)m * R_TOK + r) * DMODEL;
    uint4* hh = (uint4*)(g_aoh + rowe);
    uint4* ll = (uint4*)(g_aol + rowe);
    uint4 uz = make_uint4(0, 0, 0, 0);
    for (int i = threadIdx.x; i < DMODEL / 8; i += blockDim.x) { hh[i] = uz; ll[i] = uz; }
}

/* ---------------- prepass ---------------- */
__global__ void prep_kernel(const float* __restrict__ Wq,
                            const float* __restrict__ Wo) {
    const int NU = NMOD * DMODEL * (DMODEL / 8);
    for (int u = blockIdx.x * blockDim.x + threadIdx.x; u < NU;
         u += gridDim.x * blockDim.x) {
        int jb8 = u & (DMODEL / 8 - 1);
        int rest = u >> 8;
        int k = rest & (DMODEL - 1);
        int m = rest >> 11;
        int n0 = jb8 * 8;
        const float* src = Wq + ((size_t)(m * DMODEL + k)) * DMODEL + n0;
        float* dst = g_wqt + (size_t)m * (DMODEL / 128) * TILE_BLK
                   + (size_t)(n0 >> 7) * TILE_BLK;
        #pragma unroll
        for (int q = 0; q < 8; q++)
            dst[bpack_off(k, (n0 & 127) + q)] = f2t(src[q]);
    }
    const int NP = NMOD * (DMODEL / 2) * DMODEL;
    for (int j = blockIdx.x * blockDim.x + threadIdx.x; j < NP;
         j += gridDim.x * blockDim.x) {
        int n = j & (DMODEL - 1);
        int rest = j >> 11;
        int k2 = rest & (DMODEL / 2 - 1);
        int m = rest >> 10;
        size_t base = ((size_t)(m * DMODEL + 2 * k2)) * DMODEL + n;
        float w0 = Wo[base], w1 = Wo[base + DMODEL];
        g_woh[j] = pk2bf(w0, w1);
        g_wol[j] = pk2bf(bfres(w0), bfres(w1));
    }
}
__global__ void wsum_kernel(const float* __restrict__ Wk,
                            const float* __restrict__ Wv) {
    const int NU = NMOD * DMODEL * (KVE / 8);
    for (int u = blockIdx.x * blockDim.x + threadIdx.x; u < 2 * NU;
         u += gridDim.x * blockDim.x) {
        int isV = u >= NU;
        int v = isV ? u - NU : u;
        int jb8 = v & (KVE / 8 - 1);
        int rest = v >> 6;
        int k = rest & (DMODEL - 1);
        int m = rest >> 11;
        int n0 = jb8 * 8;
        const float* W = isV ? Wv : Wk;
        size_t sbase = ((size_t)m * 2 * DMODEL + k) * KVE + n0;
        float* dst = (isV ? g_wv : g_wk) + (size_t)m * (KVE / 128) * TILE_BLK
                   + (size_t)(n0 >> 7) * TILE_BLK;
        #pragma unroll
        for (int q = 0; q < 8; q++)
            dst[bpack_off(k, (n0 & 127) + q)] =
                f2t(W[sbase + q] + W[sbase + (size_t)DMODEL * KVE + q]);
    }
}

/* ---------------- packed tf32 GEMM core, k32 epochs, 2 CTA/SM ------------- */
__device__ __forceinline__ void gemm_tf32p(
    const float* __restrict__ Xp, const float* __restrict__ Wp,
    float (&acc)[4][4][4], float* smem)
{
    const int tid = threadIdx.x;
    const int lane = tid & 31, w = tid >> 5;
    const int wg = (w >> 2) * 4;
    const int jb0 = (w & 3) * 4;
    float* As = smem;              /* 2 stages x 4096 floats */
    float* Bs = smem + 8192;
    const unsigned sA = (unsigned)__cvta_generic_to_shared(As);
    const unsigned sB = (unsigned)__cvta_generic_to_shared(Bs);

    auto issue = [&](int buf, int k0) {
        const float* aS = Xp + (k0 >> 3) * 1024;
        const float* bS = Wp + (k0 >> 3) * 1024;
        unsigned aD = sA + buf * 16384, bD = sB + buf * 16384;
        #pragma unroll
        for (int q = 0; q < 4; q++) {
            CP16(aD + (tid + q * 256) * 16, aS + (tid + q * 256) * 4);
            CP16(bD + (tid + q * 256) * 16, bS + (tid + q * 256) * 4);
        }
        CP_COMMIT();
    };

    issue(0, 0);
    const int T = DMODEL / 32;     /* 64 epochs */
    for (int t = 0; t < T; t++) {
        const int buf = t & 1;
        if (t + 1 < T) { issue(buf ^ 1, (t + 1) * 32); CP_WAIT(1); }
        else           { CP_WAIT(0); }
        __syncthreads();
        #pragma unroll
        for (int kb = 0; kb < 4; kb++) {
            const float* Ab = As + buf * 4096 + kb * 1024;
            const float* Bb = Bs + buf * 4096 + kb * 1024;
            unsigned a[4][4], b[4][2];
            #pragma unroll
            for (int i = 0; i < 4; i++) {
                float4 v = *(const float4*)&Ab[(wg + i) * 128 + lane * 4];
                a[i][0] = __float_as_uint(v.x);
                a[i][1] = __float_as_uint(v.y);
                a[i][2] = __float_as_uint(v.z);
                a[i][3] = __float_as_uint(v.w);
            }
            #pragma unroll
            for (int j = 0; j < 4; j++) {
                float2 u = *(const float2*)&Bb[(jb0 + j) * 64 + lane * 2];
                b[j][0] = __float_as_uint(u.x);
                b[j][1] = __float_as_uint(u.y);
            }
            #pragma unroll
            for (int i = 0; i < 4; i++)
                #pragma unroll
                for (int j = 0; j < 4; j++)
                    mma_tf32(acc[i][j], a[i], b[j]);
        }
        __syncthreads();
    }
}

/* ---------------- Q projection + RoPE ---------------- */
__global__ void __launch_bounds__(256, 2) proj_q_kernel(
    const float* __restrict__ fc)
{
    extern __shared__ __align__(16) float smem[];
    const int m = blockIdx.z;
    const int cnt = g_cnt[m];
    const int row0 = blockIdx.y * BM, col0 = blockIdx.x * BN;
    if (row0 >= cnt) return;
    float acc[4][4][4] = {};
    gemm_tf32p(g_xt + (size_t)m * R_TOK * DMODEL + (size_t)(row0 >> 7) * TILE_BLK,
               g_wqt + (size_t)m * (DMODEL / 128) * TILE_BLK
                     + (size_t)(col0 >> 7) * TILE_BLK,
               acc, smem);

    const int lane = threadIdx.x & 31, w = threadIdx.x >> 5;
    const int wm = (w >> 2) * 64, wn = (w & 3) * 32;
    const int gid = lane >> 2, tig = lane & 3;
    #pragma unroll
    for (int i = 0; i < 4; i++) {
        #pragma unroll
        for (int half = 0; half < 2; half++) {
            int r = row0 + wm + i * 16 + gid + half * 8;
            if (r >= cnt) continue;
            int tok = g_tok[m * R_TOK + r];
            int b_ = tok >> 11, s = tok & (SEQ - 1);
            #pragma unroll
            for (int j = 0; j < 4; j++) {
                int c = col0 + wn + j * 8 + tig * 2;
                float e = acc[i][j][half * 2 + 0];
                float o = acc[i][j][half * 2 + 1];
                int h = c >> 7, d = c & 127, pr = d >> 1;
                float cv = fc[(size_t)s * 256 + pr * 4 + 0];
                float sv = fc[(size_t)s * 256 + pr * 4 + 2];
                size_t base = (((size_t)b_ * NH + h) * SEQ + s) * HD + d;
                g_q[base]     = e * cv + o * sv;
                g_q[base + 1] = o * cv - e * sv;
            }
        }
    }
}

/* ---------------- K/V projection (+RoPE on K); writes PRE-ROUNDED tf32 ---- */
__global__ void __launch_bounds__(256, 2) proj_kv_kernel(
    const float* __restrict__ fc)
{
    extern __shared__ __align__(16) float smem[];
    const int m = blockIdx.z;
    const int cnt = g_cnt[m];
    const int row0 = blockIdx.y * BM;
    if (row0 >= cnt) return;
    const int n0 = blockIdx.x * BN;
    const bool isV = (n0 >= KVE);
    const int c0base = isV ? n0 - KVE : n0;
    const float* Wp = (isV ? g_wv : g_wk)
                    + (size_t)m * (KVE / 128) * TILE_BLK
                    + (size_t)(c0base >> 7) * TILE_BLK;

    float acc[4][4][4] = {};
    gemm_tf32p(g_xt + (size_t)m * R_TOK * DMODEL + (size_t)(row0 >> 7) * TILE_BLK,
               Wp, acc, smem);

    const int lane = threadIdx.x & 31, w = threadIdx.x >> 5;
    const int wm = (w >> 2) * 64, wn = (w & 3) * 32;
    const int gid = lane >> 2, tig = lane & 3;
    #pragma unroll
    for (int i = 0; i < 4; i++) {
        #pragma unroll
        for (int half = 0; half < 2; half++) {
            int r = row0 + wm + i * 16 + gid + half * 8;
            if (r >= cnt) continue;
            int tok = g_tok[m * R_TOK + r];
            int b_ = tok >> 11, s = tok & (SEQ - 1);
            #pragma unroll
            for (int j = 0; j < 4; j++) {
                int c = c0base + wn + j * 8 + tig * 2;
                int kvh = c >> 7, d = c & 127;
                float e = acc[i][j][half * 2 + 0];
                float o = acc[i][j][half * 2 + 1];
                size_t base = (((size_t)b_ * NKV + kvh) * SEQ + s) * HD + d;
                if (!isV) {
                    int pr = d >> 1;
                    float cv = fc[(size_t)s * 256 + pr * 4 + 0];
                    float sv = fc[(size_t)s * 256 + pr * 4 + 2];
                    g_k[base]     = f2t(e * cv + o * sv);
                    g_k[base + 1] = f2t(o * cv - e * sv);
                } else {
                    g_v[base]     = f2t(e);
                    g_v[base + 1] = f2t(o);
                }
            }
        }
    }
}

/* ---------------- flash attention: 128 q-rows/CTA, 8 warps ---------------- */
#define KP 132
#define VP 136
#define PP 68
#define ATTN_SMEM ((64*KP + 64*VP + 128*PP) * 4)

__global__ void __launch_bounds__(256) attn_kernel() {
    extern __shared__ float sm[];
    float* Ks = sm;
    float* Vs = Ks + 64 * KP;
    float* Ps = Vs + 64 * VP;

    const int qt = blockIdx.x, h = blockIdx.y, b = blockIdx.z;
    const int kvh = h >> 2;
    const int tid = threadIdx.x;
    const int w = tid >> 5, lane = tid & 31, gid = lane >> 2, tig = lane & 3;
    const float scale = 0.08838834764831845f;

    const float* Qg = g_q + (((size_t)b * NH + h) * SEQ + qt * 128 + w * 16) * HD;
    unsigned QA[16][4];
    #pragma unroll
    for (int ks = 0; ks < 16; ks++) {
        QA[ks][0] = f2tu(Qg[gid * HD + 8 * ks + tig] * scale);
        QA[ks][1] = f2tu(Qg[(gid + 8) * HD + 8 * ks + tig] * scale);
        QA[ks][2] = f2tu(Qg[gid * HD + 8 * ks + tig + 4] * scale);
        QA[ks][3] = f2tu(Qg[(gid + 8) * HD + 8 * ks + tig + 4] * scale);
    }

    float o[16][4];
    #pragma unroll
    for (int n = 0; n < 16; n++)
        #pragma unroll
        for (int q = 0; q < 4; q++) o[n][q] = 0.f;
    float mo[2] = {-1e30f, -1e30f}, l[2] = {0.f, 0.f};

    const float* Kg = g_k + ((size_t)b * NKV + kvh) * SEQ * HD;
    const float* Vg = g_v + ((size_t)b * NKV + kvh) * SEQ * HD;
    float* Pw = Ps + w * 16 * PP;

    for (int kt = 0; kt < SEQ / 64; kt++) {
        __syncthreads();
        const float* Kt = Kg + (size_t)kt * 64 * HD;
        const float* Vt = Vg + (size_t)kt * 64 * HD;
        /* K/V already tf32-rounded at projection write: straight copy */
        #pragma unroll
        for (int it = 0; it < 8; it++) {
            int i = tid + it * 256;
            int r = i >> 5, c4 = (i & 31) << 2;
            *(float4*)&Ks[r * KP + c4] = *(const float4*)&Kt[r * HD + c4];
            *(float4*)&Vs[r * VP + c4] = *(const float4*)&Vt[r * HD + c4];
        }
        __syncthreads();

        float s[8][4] = {};
        #pragma unroll
        for (int ks = 0; ks < 16; ks++) {
            #pragma unroll
            for (int j = 0; j < 8; j++) {
                unsigned b2[2];
                b2[0] = __float_as_uint(Ks[(j * 8 + gid) * KP + ks * 8 + tig]);
                b2[1] = __float_as_uint(Ks[(j * 8 + gid) * KP + ks * 8 + tig + 4]);
                mma_tf32(s[j], QA[ks], b2);
            }
        }

        #pragma unroll
        for (int rr = 0; rr < 2; rr++) {
            float mx = -1e30f;
            #pragma unroll
            for (int j = 0; j < 8; j++)
                mx = fmaxf(mx, fmaxf(s[j][2 * rr], s[j][2 * rr + 1]));
            mx = fmaxf(mx, __shfl_xor_sync(0xffffffffu, mx, 1));
            mx = fmaxf(mx, __shfl_xor_sync(0xffffffffu, mx, 2));
            float mnew = fmaxf(mo[rr], mx);
            float corr = __expf(mo[rr] - mnew);
            float rs = 0.f;
            #pragma unroll
            for (int j = 0; j < 8; j++) {
                float p0 = f2t(__expf(s[j][2 * rr] - mnew));
                float p1 = f2t(__expf(s[j][2 * rr + 1] - mnew));
                s[j][2 * rr] = p0; s[j][2 * rr + 1] = p1;
                rs += p0 + p1;
            }
            rs += __shfl_xor_sync(0xffffffffu, rs, 1);
            rs += __shfl_xor_sync(0xffffffffu, rs, 2);
            l[rr] = l[rr] * corr + rs;
            mo[rr] = mnew;
            #pragma unroll
            for (int n = 0; n < 16; n++) {
                o[n][2 * rr] *= corr; o[n][2 * rr + 1] *= corr;
            }
        }

        #pragma unroll
        for (int j = 0; j < 8; j++) {
            *(float2*)&Pw[gid * PP + j * 8 + 2 * tig] =
                make_float2(s[j][0], s[j][1]);
            *(float2*)&Pw[(gid + 8) * PP + j * 8 + 2 * tig] =
                make_float2(s[j][2], s[j][3]);
        }
        __syncwarp();

        #pragma unroll
        for (int kk = 0; kk < 8; kk++) {
            unsigned a[4];
            a[0] = __float_as_uint(Pw[gid * PP + kk * 8 + tig]);
            a[1] = __float_as_uint(Pw[(gid + 8) * PP + kk * 8 + tig]);
            a[2] = __float_as_uint(Pw[gid * PP + kk * 8 + tig + 4]);
            a[3] = __float_as_uint(Pw[(gid + 8) * PP + kk * 8 + tig + 4]);
            #pragma unroll
            for (int n = 0; n < 16; n++) {
                unsigned b2[2];
                b2[0] = __float_as_uint(Vs[(kk * 8 + tig) * VP + n * 8 + gid]);
                b2[1] = __float_as_uint(Vs[(kk * 8 + tig + 4) * VP + n * 8 + gid]);
                mma_tf32(o[n], a, b2);
            }
        }
    }

    int t0 = b * SEQ + qt * 128 + w * 16 + gid;
    int t1 = t0 + 8;
    size_t r0 = (size_t)g_slot[t0] * DMODEL + h * HD;
    size_t r1 = (size_t)g_slot[t1] * DMODEL + h * HD;
    unsigned* AH = (unsigned*)g_aoh;
    unsigned* AL = (unsigned*)g_aol;
    float inv0 = 1.f / l[0], inv1 = 1.f / l[1];
    #pragma unroll
    for (int n = 0; n < 16; n++) {
        float v0 = o[n][0] * inv0, v1 = o[n][1] * inv0;
        float v2 = o[n][2] * inv1, v3 = o[n][3] * inv1;
        size_t i0 = (r0 + n * 8 + 2 * tig) >> 1;
        size_t i1 = (r1 + n * 8 + 2 * tig) >> 1;
        AH[i0] = pk2bf(v0, v1);
        AL[i0] = pk2bf(bfres(v0), bfres(v1));
        AH[i1] = pk2bf(v2, v3);
        AL[i1] = pk2bf(bfres(v2), bfres(v3));
    }
}

/* ---------------- output projection: bf16x3 ---------------- */
#define OAP 12
#define OBP 132
#define OASZ (128*OAP)
#define OBSZ (8*OBP)

__global__ void __launch_bounds__(256, 2) proj_o_kernel(float* __restrict__ out)
{
    __shared__ unsigned sAh[2 * OASZ];
    __shared__ unsigned sAl[2 * OASZ];
    __shared__ unsigned sBh[2 * OBSZ];
    __shared__ unsigned sBl[2 * OBSZ];

    const int m = blockIdx.z;
    const int cnt = g_cnt[m];
    const int row0 = blockIdx.y * BM, col0 = blockIdx.x * BN;
    if (row0 >= cnt) return;

    const __nv_bfloat16* Xh = g_aoh + (size_t)m * R_TOK * DMODEL;
    const __nv_bfloat16* Xl = g_aol + (size_t)m * R_TOK * DMODEL;
    const unsigned* Wh = g_woh + (size_t)m * (DMODEL / 2) * DMODEL;
    const unsigned* Wl = g_wol + (size_t)m * (DMODEL / 2) * DMODEL;

    const int tid = threadIdx.x;
    const int lane = tid & 31, w = tid >> 5;
    const int wm = (w >> 2) * 64, wn = (w & 3) * 32;
    const int gid = lane >> 2, tig = lane & 3;

    const unsigned bAh = (unsigned)__cvta_generic_to_shared(sAh);
    const unsigned bAl = (unsigned)__cvta_generic_to_shared(sAl);
    const unsigned bBh = (unsigned)__cvta_generic_to_shared(sBh);
    const unsigned bBl = (unsigned)__cvta_generic_to_shared(sBl);

    const int arow = tid >> 1, ahalf = tid & 1;
    const int bkp = tid >> 5, bnq = tid & 31;

    auto issue = [&](int buf, int k0) {
        size_t aoff = (size_t)(row0 + arow) * DMODEL + k0 + ahalf * 8;
        unsigned adst = (unsigned)(buf * OASZ + arow * OAP + ahalf * 4) * 4;
        CP16(bAh + adst, Xh + aoff);
        CP16(bAl + adst, Xl + aoff);
        size_t boff = (size_t)((k0 >> 1) + bkp) * DMODEL + col0 + bnq * 4;
        unsigned bdst = (unsigned)(buf * OBSZ + bkp * OBP + bnq * 4) * 4;
        CP16(bBh + bdst, Wh + boff);
        CP16(bBl + bdst, Wl + boff);
        CP_COMMIT();
    };

    float acc[4][4][4] = {};
    issue(0, 0);
    const int T = DMODEL / 16;
    for (int t = 0; t < T; t++) {
        const int buf = t & 1;
        if (t + 1 < T) { issue(buf ^ 1, (t + 1) * 16); CP_WAIT(1); }
        else           { CP_WAIT(0); }
        __syncthreads();
        const unsigned* Ah = sAh + buf * OASZ;
        const unsigned* Al = sAl + buf * OASZ;
        const unsigned* Bh = sBh + buf * OBSZ;
        const unsigned* Bl = sBl + buf * OBSZ;

        unsigned ah[4][4], bh[4][2];
        #pragma unroll
        for (int i = 0; i < 4; i++) {
            int rb = (wm + i * 16 + gid) * OAP;
            ah[i][0] = Ah[rb + tig];
            ah[i][1] = Ah[rb + 8 * OAP + tig];
            ah[i][2] = Ah[rb + tig + 4];
            ah[i][3] = Ah[rb + 8 * OAP + tig + 4];
        }
        #pragma unroll
        for (int j = 0; j < 4; j++) {
            int cb = wn + j * 8 + gid;
            bh[j][0] = Bh[tig * OBP + cb];
            bh[j][1] = Bh[(tig + 4) * OBP + cb];
        }
        #pragma unroll
        for (int i = 0; i < 4; i++)
            #pragma unroll
            for (int j = 0; j < 4; j++)
                mma_bf16(acc[i][j], ah[i], bh[j]);

        unsigned bl[4][2];
        #pragma unroll
        for (int j = 0; j < 4; j++) {
            int cb = wn + j * 8 + gid;
            bl[j][0] = Bl[tig * OBP + cb];
            bl[j][1] = Bl[(tig + 4) * OBP + cb];
        }
        #pragma unroll
        for (int i = 0; i < 4; i++)
            #pragma unroll
            for (int j = 0; j < 4; j++)
                mma_bf16(acc[i][j], ah[i], bl[j]);

        unsigned al[4][4];
        #pragma unroll
        for (int i = 0; i < 4; i++) {
            int rb = (wm + i * 16 + gid) * OAP;
            al[i][0] = Al[rb + tig];
            al[i][1] = Al[rb + 8 * OAP + tig];
            al[i][2] = Al[rb + tig + 4];
            al[i][3] = Al[rb + 8 * OAP + tig + 4];
        }
        #pragma unroll
        for (int i = 0; i < 4; i++)
            #pragma unroll
            for (int j = 0; j < 4; j++)
                mma_bf16(acc[i][j], al[i], bh[j]);

        __syncthreads();
    }

    #pragma unroll
    for (int i = 0; i < 4; i++) {
        #pragma unroll
        for (int half = 0; half < 2; half++) {
            int r = row0 + wm + i * 16 + gid + half * 8;
            if (r >= cnt) continue;
            int tok = g_tok[m * R_TOK + r];
            #pragma unroll
            for (int j = 0; j < 4; j++) {
                int c = col0 + wn + j * 8 + tig * 2;
                out[(size_t)tok * DMODEL + c]     = acc[i][j][half * 2 + 0];
                out[(size_t)tok * DMODEL + c + 1] = acc[i][j][half * 2 + 1];
            }
        }
    }
}

/* ---------------- launch (multi-stream fork/join, graph-capturable) ------- */
extern "C" void kernel_launch(void* const* d_in, const int* in_sizes, int n_in,
                              void* d_out, int out_size) {
    (void)in_sizes; (void)n_in; (void)out_size;
    const float* x  = (const float*)d_in[0];
    const float* fc = (const float*)d_in[1];
    const float* Wq = (const float*)d_in[2];
    const float* Wk = (const float*)d_in[3];
    const float* Wv = (const float*)d_in[4];
    const float* Wo = (const float*)d_in[5];
    const int*   mid = (const int*)d_in[6];
    float* out = (float*)d_out;

    static cudaStream_t s1, s2, s3;
    static cudaEvent_t eRoot, ePrep, eAssign, eGather, ePad, eKV;
    static int init_done = 0;
    if (!init_done) {
        cudaFuncSetAttribute(attn_kernel,
            cudaFuncAttributeMaxDynamicSharedMemorySize, ATTN_SMEM);
        cudaFuncSetAttribute(proj_q_kernel,
            cudaFuncAttributeMaxDynamicSharedMemorySize, GEMM_SMEM2);
        cudaFuncSetAttribute(proj_kv_kernel,
            cudaFuncAttributeMaxDynamicSharedMemorySize, GEMM_SMEM2);
        cudaStreamCreateWithFlags(&s1, cudaStreamNonBlocking);
        cudaStreamCreateWithFlags(&s2, cudaStreamNonBlocking);
        cudaStreamCreateWithFlags(&s3, cudaStreamNonBlocking);
        cudaEventCreateWithFlags(&eRoot,   cudaEventDisableTiming);
        cudaEventCreateWithFlags(&ePrep,   cudaEventDisableTiming);
        cudaEventCreateWithFlags(&eAssign, cudaEventDisableTiming);
        cudaEventCreateWithFlags(&eGather, cudaEventDisableTiming);
        cudaEventCreateWithFlags(&ePad,    cudaEventDisableTiming);
        cudaEventCreateWithFlags(&eKV,     cudaEventDisableTiming);
        init_done = 1;
    }

    cudaStream_t s0 = 0;   /* legacy default stream (capture origin) */

    /* fork */
    cudaEventRecord(eRoot, s0);
    cudaStreamWaitEvent(s1, eRoot, 0);
    cudaStreamWaitEvent(s2, eRoot, 0);
    cudaStreamWaitEvent(s3, eRoot, 0);

    /* s1: weight prep (Wq pack + Wo bf16 split) */
    prep_kernel<<<4096, 256, 0, s1>>>(Wq, Wo);
    cudaEventRecord(ePrep, s1);

    /* s2: Wk/Wv sum-pack, later proj_kv */
    wsum_kernel<<<2048, 256, 0, s2>>>(Wk, Wv);

    /* s0: token assignment + gather */
    zero_cnt_kernel<<<1, 32, 0, s0>>>();
    assign_kernel<<<R_TOK / 256, 256, 0, s0>>>(mid);
    cudaEventRecord(eAssign, s0);

    /* s3: pad (needs counts only) */
    cudaStreamWaitEvent(s3, eAssign, 0);
    pad_kernel<<<dim3(BM, NMOD), 256, 0, s3>>>();
    cudaEventRecord(ePad, s3);

    gather_x_kernel<<<R_TOK, 256, 0, s0>>>(x);
    cudaEventRecord(eGather, s0);

    /* s0: proj_q after prep + pad */
    cudaStreamWaitEvent(s0, ePrep, 0);
    cudaStreamWaitEvent(s0, ePad, 0);
    proj_q_kernel<<<dim3(DMODEL / BN, R_TOK / BM, NMOD), 256, GEMM_SMEM2, s0>>>(fc);

    /* s2: proj_kv after wsum + gather + pad (runs concurrent with proj_q) */
    cudaStreamWaitEvent(s2, eGather, 0);
    cudaStreamWaitEvent(s2, ePad, 0);
    proj_kv_kernel<<<dim3((2 * KVE) / BN, R_TOK / BM, NMOD), 256, GEMM_SMEM2, s2>>>(fc);
    cudaEventRecord(eKV, s2);

    /* s0: attention after proj_q (program order) + proj_kv (event) */
    cudaStreamWaitEvent(s0, eKV, 0);
    attn_kernel<<<dim3(SEQ / 128, NH, BDIM), 256, ATTN_SMEM, s0>>>();

    /* s0: output projection (prep/pad already joined into s0 above) */
    proj_o_kernel<<<dim3(DMODEL / BN, R_TOK / BM, NMOD), 256, 0, s0>>>(out);
}